// round 5
// baseline (speedup 1.0000x reference)
#include <cuda_runtime.h>
#include <cstdint>

#define H   128
#define ED  32
#define NH  4
#define DH  32
#define TD  32
#define MH  256

#define MAXN 50048
#define MAXE 640064

// ---------------- scratch (module-level device memory; no allocs) ----------
__device__ __align__(128) float    g_hq  [(size_t)MAXN * H];
__device__ __align__(128) float    g_hk  [(size_t)MAXN * H];
__device__ __align__(128) float    g_hm1 [(size_t)MAXN * H];   // h @ W1a + b1
__device__ __align__(128) float    g_scores[(size_t)MAXE * NH];
__device__ __align__(128) float    g_ex    [(size_t)MAXE * NH];
__device__ __align__(128) unsigned g_smax  [(size_t)MAXN * NH];
__device__ __align__(128) float    g_den   [(size_t)MAXN * NH];
__device__ __align__(128) float    g_agg   [(size_t)MAXN * H];

// ---------------- helpers ---------------------------------------------------
__device__ __forceinline__ unsigned enc_f(float f) {
    unsigned u = __float_as_uint(f);
    return (u & 0x80000000u) ? ~u : (u | 0x80000000u);
}
__device__ __forceinline__ float dec_f(unsigned k) {
    unsigned u = (k & 0x80000000u) ? (k & 0x7FFFFFFFu) : ~k;
    return __uint_as_float(u);
}
__device__ __forceinline__ float silu_f(float x) {
    return x / (1.0f + __expf(-x));
}
__device__ __forceinline__ void red_add_v4(float* p, float4 v) {
    asm volatile("red.global.add.v4.f32 [%0], {%1,%2,%3,%4};"
                 :: "l"(p), "f"(v.x), "f"(v.y), "f"(v.z), "f"(v.w) : "memory");
}
__device__ __forceinline__ void fma4(float4& acc, float a, const float4& b) {
    acc.x = fmaf(a, b.x, acc.x);
    acc.y = fmaf(a, b.y, acc.y);
    acc.z = fmaf(a, b.z, acc.z);
    acc.w = fmaf(a, b.w, acc.w);
}

// ============================================================================
// K1: node projections  hq = h@wq, hk = h@wk, hm1 = h@W1a + b1
// 64 rows/block, 8 rows/thread (8x weight reuse per strided LDS).
// ============================================================================
#define SMEM1_FLOATS (64 * H + 32 * H)
#define SMEM1_BYTES  (SMEM1_FLOATS * 4)

__global__ void __launch_bounds__(256) k1_proj(
    const float* __restrict__ h,
    const float* __restrict__ wq, const float* __restrict__ wk,
    const float* __restrict__ mw1, const float* __restrict__ mb1, int N)
{
    extern __shared__ float sm1[];
    float* sa = sm1;            // [64][128]
    float* sw = sm1 + 64 * H;   // [32][128]
    const int tid  = threadIdx.x;
    const int row0 = blockIdx.x * 64;

    for (int i = tid; i < 64 * H / 4; i += 256) {
        int r = i >> 5, c4 = i & 31;
        float4 v = make_float4(0.f, 0.f, 0.f, 0.f);
        if (row0 + r < N) v = ((const float4*)(h + (size_t)(row0 + r) * H))[c4];
        ((float4*)sa)[i] = v;
    }

    const int cg = tid & 31, rg = tid >> 5, c0 = cg << 2;

    #pragma unroll
    for (int m = 0; m < 3; m++) {
        const float* W = (m == 0) ? wq : (m == 1) ? wk : mw1;
        float4 acc[8];
        if (m == 2) {
            float4 b = ((const float4*)mb1)[cg];
            #pragma unroll
            for (int i = 0; i < 8; i++) acc[i] = b;
        } else {
            #pragma unroll
            for (int i = 0; i < 8; i++) acc[i] = make_float4(0.f, 0.f, 0.f, 0.f);
        }
        for (int ks = 0; ks < 4; ks++) {
            __syncthreads();
            for (int i = tid; i < 32 * H / 4; i += 256)
                ((float4*)sw)[i] = ((const float4*)(W + (size_t)ks * 32 * H))[i];
            __syncthreads();
            #pragma unroll
            for (int k4 = 0; k4 < 8; k4++) {
                float4 w0 = *(const float4*)&sw[(k4 * 4 + 0) * H + c0];
                float4 w1 = *(const float4*)&sw[(k4 * 4 + 1) * H + c0];
                float4 w2 = *(const float4*)&sw[(k4 * 4 + 2) * H + c0];
                float4 w3 = *(const float4*)&sw[(k4 * 4 + 3) * H + c0];
                #pragma unroll
                for (int i = 0; i < 8; i++) {
                    float4 a = *(const float4*)&sa[(rg * 8 + i) * H + ks * 32 + k4 * 4];
                    fma4(acc[i], a.x, w0); fma4(acc[i], a.y, w1);
                    fma4(acc[i], a.z, w2); fma4(acc[i], a.w, w3);
                }
            }
        }
        float* O = (m == 0) ? g_hq : (m == 1) ? g_hk : g_hm1;
        #pragma unroll
        for (int i = 0; i < 8; i++) {
            int r = rg * 8 + i;
            if (row0 + r < N)
                *(float4*)&O[(size_t)(row0 + r) * H + c0] = acc[i];
        }
    }
}

// ============================================================================
// K2: per-edge attention scores + segment max.
// ============================================================================
__global__ void __launch_bounds__(256) k2_scores(
    const float* __restrict__ wt,
    const float* __restrict__ tfreq, const float* __restrict__ tphase,
    const int* __restrict__ eidx, const float* __restrict__ dts, int E)
{
    __shared__ float swt[TD * H];
    __shared__ float sfreq[TD], sphase[TD];
    __shared__ __align__(16) float sdtf[8][TD];
    const int tid = threadIdx.x;
    for (int i = tid; i < TD * H / 4; i += 256)
        ((float4*)swt)[i] = ((const float4*)wt)[i];
    if (tid < TD) { sfreq[tid] = tfreq[tid]; sphase[tid] = tphase[tid]; }
    __syncthreads();

    const int warp = tid >> 5, lane = tid & 31;
    const int c0 = lane << 2;
    for (int e = blockIdx.x * 8 + warp; e < E; e += gridDim.x * 8) {
        int tgt = eidx[e];
        int src = eidx[E + e];
        float dt = dts[e];
        sdtf[warp][lane] = cosf(dt * sfreq[lane] + sphase[lane]);
        __syncwarp();

        float4 kv = *(const float4*)&g_hk[(size_t)src * H + c0];
        #pragma unroll
        for (int d4 = 0; d4 < 8; d4++) {
            float4 f = *(const float4*)&sdtf[warp][d4 * 4];
            fma4(kv, f.x, *(const float4*)&swt[(d4 * 4 + 0) * H + c0]);
            fma4(kv, f.y, *(const float4*)&swt[(d4 * 4 + 1) * H + c0]);
            fma4(kv, f.z, *(const float4*)&swt[(d4 * 4 + 2) * H + c0]);
            fma4(kv, f.w, *(const float4*)&swt[(d4 * 4 + 3) * H + c0]);
        }
        float4 q4 = *(const float4*)&g_hq[(size_t)tgt * H + c0];
        float p = q4.x * kv.x + q4.y * kv.y + q4.z * kv.z + q4.w * kv.w;
        p += __shfl_xor_sync(0xffffffffu, p, 4);
        p += __shfl_xor_sync(0xffffffffu, p, 2);
        p += __shfl_xor_sync(0xffffffffu, p, 1);
        if ((lane & 7) == 0) {
            float s = p * 0.17677669529663687f;   // 1/sqrt(32)
            int hd = lane >> 3;
            g_scores[(size_t)e * NH + hd] = s;
            atomicMax(&g_smax[(size_t)tgt * NH + hd], enc_f(s));
        }
        __syncwarp();
    }
}

// ============================================================================
// K3: ex = exp(score - smax[tgt]); den[tgt] += ex
// ============================================================================
__global__ void __launch_bounds__(256) k3_softmax(
    const int* __restrict__ eidx, int E)
{
    int e = blockIdx.x * 256 + threadIdx.x;
    if (e >= E) return;
    int tgt = eidx[e];
    float4 s4 = *(const float4*)&g_scores[(size_t)e * NH];
    uint4  m4 = *(const uint4*)&g_smax[(size_t)tgt * NH];
    float4 v;
    v.x = __expf(s4.x - dec_f(m4.x));
    v.y = __expf(s4.y - dec_f(m4.y));
    v.z = __expf(s4.z - dec_f(m4.z));
    v.w = __expf(s4.w - dec_f(m4.w));
    *(float4*)&g_ex[(size_t)e * NH] = v;
    red_add_v4(&g_den[(size_t)tgt * NH], v);
}

// ============================================================================
// K4: edge message MLP + attention-weighted scatter.
// 64-edge tiles, 8 rows/thread (8x weight reuse). 1 block/SM, persistent.
// ============================================================================
#define SMEM4_FLOATS (4096 + 16384 + 2048 + 8192 + 256 + 64)
#define SMEM4_BYTES  (SMEM4_FLOATS * 4)

__global__ void __launch_bounds__(256) k4_edge(
    const float* __restrict__ ef, const float* __restrict__ w1b,
    const float* __restrict__ w2, const float* __restrict__ b2,
    const int* __restrict__ eidx, int E)
{
    extern __shared__ float sm4[];
    float* sw1b = sm4;                 // [32][128]
    float* sw2  = sm4 + 4096;          // [128][128]
    float* sef  = sm4 + 20480;         // [64][32]
    float* shid = sm4 + 22528;         // [64][128]
    float* satt = sm4 + 30720;         // [64][4]
    int*   stgt = (int*)(sm4 + 30976); // [64]

    const int tid = threadIdx.x;
    for (int i = tid; i < 4096 / 4; i += 256)
        ((float4*)sw1b)[i] = ((const float4*)w1b)[i];
    for (int i = tid; i < 16384 / 4; i += 256)
        ((float4*)sw2)[i] = ((const float4*)w2)[i];

    const int cg = tid & 31, rg = tid >> 5, c0 = cg << 2, hd = cg >> 3;
    const float4 b2v = ((const float4*)b2)[cg];
    const int ntiles = (E + 63) >> 6;

    for (int tile = blockIdx.x; tile < ntiles; tile += gridDim.x) {
        const int e0 = tile << 6;
        __syncthreads();   // protect smem from previous tile (and weight load, tile 0)

        {   // attn + tgt for 64 edges (all 256 threads)
            int r = tid >> 2, hh = tid & 3;
            int e = e0 + r;
            float a = 0.f; int tg = 0;
            if (e < E) {
                tg = eidx[e];
                a  = g_ex[(size_t)e * NH + hh] / g_den[(size_t)tg * NH + hh];
            }
            satt[r * 4 + hh] = a;
            if (hh == 0) stgt[r] = tg;
        }
        for (int i = tid; i < 2048 / 4; i += 256) {
            int r = i >> 3, c4 = i & 7;
            int e = e0 + r;
            float4 v = make_float4(0.f, 0.f, 0.f, 0.f);
            if (e < E) v = ((const float4*)(ef + (size_t)e * ED))[c4];
            ((float4*)sef)[i] = v;
        }
        __syncthreads();

        // phase A: pre-activation = hm1[src] + ef @ W1b, then silu -> shid
        float4 acc[8];
        #pragma unroll
        for (int i = 0; i < 8; i++) {
            int e = e0 + rg * 8 + i;
            int src = (e < E) ? eidx[E + e] : 0;
            acc[i] = *(const float4*)&g_hm1[(size_t)src * H + c0];
        }
        #pragma unroll
        for (int d4 = 0; d4 < 8; d4++) {
            float4 w0 = *(const float4*)&sw1b[(d4 * 4 + 0) * H + c0];
            float4 w1 = *(const float4*)&sw1b[(d4 * 4 + 1) * H + c0];
            float4 wz = *(const float4*)&sw1b[(d4 * 4 + 2) * H + c0];
            float4 w3 = *(const float4*)&sw1b[(d4 * 4 + 3) * H + c0];
            #pragma unroll
            for (int i = 0; i < 8; i++) {
                float4 a = *(const float4*)&sef[(rg * 8 + i) * ED + d4 * 4];
                fma4(acc[i], a.x, w0); fma4(acc[i], a.y, w1);
                fma4(acc[i], a.z, wz); fma4(acc[i], a.w, w3);
            }
        }
        #pragma unroll
        for (int i = 0; i < 8; i++) {
            float4 s;
            s.x = silu_f(acc[i].x); s.y = silu_f(acc[i].y);
            s.z = silu_f(acc[i].z); s.w = silu_f(acc[i].w);
            *(float4*)&shid[(rg * 8 + i) * H + c0] = s;
        }
        __syncthreads();

        // phase B: m = hid @ msg_w2 + b2  (8 rows/thread, weight reused 8x)
        float4 m4[8];
        #pragma unroll
        for (int i = 0; i < 8; i++) m4[i] = b2v;
        #pragma unroll 4
        for (int k4 = 0; k4 < 32; k4++) {
            float4 w0 = *(const float4*)&sw2[(k4 * 4 + 0) * H + c0];
            float4 w1 = *(const float4*)&sw2[(k4 * 4 + 1) * H + c0];
            float4 wz = *(const float4*)&sw2[(k4 * 4 + 2) * H + c0];
            float4 w3 = *(const float4*)&sw2[(k4 * 4 + 3) * H + c0];
            #pragma unroll
            for (int i = 0; i < 8; i++) {
                float4 a = *(const float4*)&shid[(rg * 8 + i) * H + k4 * 4];
                fma4(m4[i], a.x, w0); fma4(m4[i], a.y, w1);
                fma4(m4[i], a.z, wz); fma4(m4[i], a.w, w3);
            }
        }
        // phase C: scatter attn * m
        #pragma unroll
        for (int i = 0; i < 8; i++) {
            int r = rg * 8 + i, e = e0 + r;
            if (e < E) {
                float a  = satt[r * 4 + hd];
                int   tg = stgt[r];
                float4 v = make_float4(a * m4[i].x, a * m4[i].y,
                                       a * m4[i].z, a * m4[i].w);
                red_add_v4(&g_agg[(size_t)tg * H + c0], v);
            }
        }
    }
}

// ============================================================================
// K5: per-node output:  aggregated = agg@wo ; x=[h||aggregated||t_feat] ;
//     dh = (silu(silu(x@w1+b1)@w2+b2))@w3 + b3
// ============================================================================
#define SMEM5_FLOATS (9216 + 8192 + 8192)
#define SMEM5_BYTES  (SMEM5_FLOATS * 4)

__global__ void __launch_bounds__(256) k5_out(
    const float* __restrict__ h,  const float* __restrict__ wo,
    const float* __restrict__ w1, const float* __restrict__ b1,
    const float* __restrict__ w2, const float* __restrict__ b2,
    const float* __restrict__ w3, const float* __restrict__ b3,
    const float* __restrict__ tptr,
    const float* __restrict__ tfreq, const float* __restrict__ tphase,
    float* __restrict__ out, int N)
{
    extern __shared__ float sm5[];
    float* sx = sm5;                 // [32][288]
    float* sy = sm5 + 9216;          // [32][256]
    float* sw = sm5 + 9216 + 8192;   // up to [32][256]

    const int tid  = threadIdx.x;
    const int row0 = blockIdx.x * 32;
    const float t  = tptr[0];

    for (int i = tid; i < 32 * TD; i += 256) {
        int r = i >> 5, j = i & 31;
        sx[r * 288 + 256 + j] = cosf(t * tfreq[j] + tphase[j]);
    }
    for (int i = tid; i < 32 * H / 4; i += 256) {
        int r = i >> 5, c4 = i & 31;
        float4 v = make_float4(0.f, 0.f, 0.f, 0.f);
        if (row0 + r < N) v = ((const float4*)(h + (size_t)(row0 + r) * H))[c4];
        *(float4*)&sx[r * 288 + c4 * 4] = v;
    }
    for (int i = tid; i < 32 * H / 4; i += 256) {
        int r = i >> 5, c4 = i & 31;
        float4 v = make_float4(0.f, 0.f, 0.f, 0.f);
        if (row0 + r < N) v = ((const float4*)(g_agg + (size_t)(row0 + r) * H))[c4];
        ((float4*)sy)[i] = v;
    }
    __syncthreads();

    const int cg = tid & 31, rg = tid >> 5, c0 = cg << 2;

    // stage 0: aggregated = aggtile @ wo  -> sx[:, 128:256]
    {
        float4 acc[4];
        #pragma unroll
        for (int i = 0; i < 4; i++) acc[i] = make_float4(0.f, 0.f, 0.f, 0.f);
        for (int ks = 0; ks < 4; ks++) {
            __syncthreads();
            for (int i = tid; i < 32 * H / 4; i += 256)
                ((float4*)sw)[i] = ((const float4*)(wo + (size_t)ks * 32 * H))[i];
            __syncthreads();
            #pragma unroll
            for (int k4 = 0; k4 < 8; k4++) {
                float4 w0 = *(const float4*)&sw[(k4 * 4 + 0) * H + c0];
                float4 w1 = *(const float4*)&sw[(k4 * 4 + 1) * H + c0];
                float4 wz = *(const float4*)&sw[(k4 * 4 + 2) * H + c0];
                float4 w3 = *(const float4*)&sw[(k4 * 4 + 3) * H + c0];
                #pragma unroll
                for (int i = 0; i < 4; i++) {
                    float4 a = *(const float4*)&sy[(rg * 4 + i) * H + ks * 32 + k4 * 4];
                    fma4(acc[i], a.x, w0); fma4(acc[i], a.y, w1);
                    fma4(acc[i], a.z, wz); fma4(acc[i], a.w, w3);
                }
            }
        }
        __syncthreads();
        #pragma unroll
        for (int i = 0; i < 4; i++)
            *(float4*)&sx[(rg * 4 + i) * 288 + 128 + c0] = acc[i];
    }
    __syncthreads();

    const int cgB = tid & 63, rgB = tid >> 6, cB0 = cgB << 2;

    // stage 1: y1 = silu(x @ w1 + b1) -> sy [32][256]
    {
        float4 acc[8];
        float4 bb = ((const float4*)b1)[cgB];
        #pragma unroll
        for (int i = 0; i < 8; i++) acc[i] = bb;
        for (int ks = 0; ks < 9; ks++) {
            __syncthreads();
            for (int i = tid; i < 32 * MH / 4; i += 256)
                ((float4*)sw)[i] = ((const float4*)(w1 + (size_t)ks * 32 * MH))[i];
            __syncthreads();
            #pragma unroll
            for (int k4 = 0; k4 < 8; k4++) {
                float4 w0 = *(const float4*)&sw[(k4 * 4 + 0) * MH + cB0];
                float4 w1v = *(const float4*)&sw[(k4 * 4 + 1) * MH + cB0];
                float4 wz = *(const float4*)&sw[(k4 * 4 + 2) * MH + cB0];
                float4 w3 = *(const float4*)&sw[(k4 * 4 + 3) * MH + cB0];
                #pragma unroll
                for (int i = 0; i < 8; i++) {
                    float4 a = *(const float4*)&sx[(rgB * 8 + i) * 288 + ks * 32 + k4 * 4];
                    fma4(acc[i], a.x, w0); fma4(acc[i], a.y, w1v);
                    fma4(acc[i], a.z, wz); fma4(acc[i], a.w, w3);
                }
            }
        }
        __syncthreads();
        #pragma unroll
        for (int i = 0; i < 8; i++) {
            float4 s;
            s.x = silu_f(acc[i].x); s.y = silu_f(acc[i].y);
            s.z = silu_f(acc[i].z); s.w = silu_f(acc[i].w);
            *(float4*)&sy[(rgB * 8 + i) * MH + cB0] = s;
        }
    }
    __syncthreads();

    // stage 2: y2 = silu(y1 @ w2 + b2) -> sx rows (stride 288), cols 0:256
    {
        float4 acc[8];
        float4 bb = ((const float4*)b2)[cgB];
        #pragma unroll
        for (int i = 0; i < 8; i++) acc[i] = bb;
        for (int ks = 0; ks < 8; ks++) {
            __syncthreads();
            for (int i = tid; i < 32 * MH / 4; i += 256)
                ((float4*)sw)[i] = ((const float4*)(w2 + (size_t)ks * 32 * MH))[i];
            __syncthreads();
            #pragma unroll
            for (int k4 = 0; k4 < 8; k4++) {
                float4 w0 = *(const float4*)&sw[(k4 * 4 + 0) * MH + cB0];
                float4 w1v = *(const float4*)&sw[(k4 * 4 + 1) * MH + cB0];
                float4 wz = *(const float4*)&sw[(k4 * 4 + 2) * MH + cB0];
                float4 w3 = *(const float4*)&sw[(k4 * 4 + 3) * MH + cB0];
                #pragma unroll
                for (int i = 0; i < 8; i++) {
                    float4 a = *(const float4*)&sy[(rgB * 8 + i) * MH + ks * 32 + k4 * 4];
                    fma4(acc[i], a.x, w0); fma4(acc[i], a.y, w1v);
                    fma4(acc[i], a.z, wz); fma4(acc[i], a.w, w3);
                }
            }
        }
        __syncthreads();
        #pragma unroll
        for (int i = 0; i < 8; i++) {
            float4 s;
            s.x = silu_f(acc[i].x); s.y = silu_f(acc[i].y);
            s.z = silu_f(acc[i].z); s.w = silu_f(acc[i].w);
            *(float4*)&sx[(rgB * 8 + i) * 288 + cB0] = s;
        }
    }
    __syncthreads();

    // stage 3: out = y2 @ w3 + b3
    {
        float4 acc[4];
        float4 bb = ((const float4*)b3)[cg];
        #pragma unroll
        for (int i = 0; i < 4; i++) acc[i] = bb;
        for (int ks = 0; ks < 8; ks++) {
            __syncthreads();
            for (int i = tid; i < 32 * H / 4; i += 256)
                ((float4*)sw)[i] = ((const float4*)(w3 + (size_t)ks * 32 * H))[i];
            __syncthreads();
            #pragma unroll
            for (int k4 = 0; k4 < 8; k4++) {
                float4 w0 = *(const float4*)&sw[(k4 * 4 + 0) * H + c0];
                float4 w1v = *(const float4*)&sw[(k4 * 4 + 1) * H + c0];
                float4 wz = *(const float4*)&sw[(k4 * 4 + 2) * H + c0];
                float4 w3v = *(const float4*)&sw[(k4 * 4 + 3) * H + c0];
                #pragma unroll
                for (int i = 0; i < 4; i++) {
                    float4 a = *(const float4*)&sx[(rg * 4 + i) * 288 + ks * 32 + k4 * 4];
                    fma4(acc[i], a.x, w0); fma4(acc[i], a.y, w1v);
                    fma4(acc[i], a.z, wz); fma4(acc[i], a.w, w3v);
                }
            }
        }
        #pragma unroll
        for (int i = 0; i < 4; i++) {
            int r = rg * 4 + i;
            if (row0 + r < N)
                *(float4*)&out[(size_t)(row0 + r) * H + c0] = acc[i];
        }
    }
}

// ============================================================================
extern "C" void kernel_launch(void* const* d_in, const int* in_sizes, int n_in,
                              void* d_out, int out_size)
{
    int wbase = (in_sizes[5] == (H + ED) * H) ? 5 : 6;

    const float* t_ptr  = (const float*)d_in[0];
    const float* h      = (const float*)d_in[1];
    const int*   eidx   = (const int*)  d_in[2];
    const float* ef     = (const float*)d_in[3];
    const float* dts    = (const float*)d_in[4];
    const float* msg_w1 = (const float*)d_in[wbase + 0];
    const float* msg_b1 = (const float*)d_in[wbase + 1];
    const float* msg_w2 = (const float*)d_in[wbase + 2];
    const float* msg_b2 = (const float*)d_in[wbase + 3];
    const float* wq     = (const float*)d_in[wbase + 4];
    const float* wk     = (const float*)d_in[wbase + 5];
    const float* wt     = (const float*)d_in[wbase + 6];
    const float* wo     = (const float*)d_in[wbase + 7];
    const float* tfreq  = (const float*)d_in[wbase + 8];
    const float* tphase = (const float*)d_in[wbase + 9];
    const float* nw1    = (const float*)d_in[wbase + 10];
    const float* nb1    = (const float*)d_in[wbase + 11];
    const float* nw2    = (const float*)d_in[wbase + 12];
    const float* nb2    = (const float*)d_in[wbase + 13];
    const float* nw3    = (const float*)d_in[wbase + 14];
    const float* nb3    = (const float*)d_in[wbase + 15];
    float* out = (float*)d_out;

    const int N = in_sizes[1] / H;
    const int E = in_sizes[4];

    void *p_smax, *p_den, *p_agg;
    cudaGetSymbolAddress(&p_smax, g_smax);
    cudaGetSymbolAddress(&p_den,  g_den);
    cudaGetSymbolAddress(&p_agg,  g_agg);
    cudaMemsetAsync(p_smax, 0, (size_t)N * NH * sizeof(unsigned), 0);
    cudaMemsetAsync(p_den,  0, (size_t)N * NH * sizeof(float), 0);
    cudaMemsetAsync(p_agg,  0, (size_t)N * H  * sizeof(float), 0);

    cudaFuncSetAttribute(k1_proj, cudaFuncAttributeMaxDynamicSharedMemorySize, SMEM1_BYTES);
    cudaFuncSetAttribute(k4_edge, cudaFuncAttributeMaxDynamicSharedMemorySize, SMEM4_BYTES);
    cudaFuncSetAttribute(k5_out,  cudaFuncAttributeMaxDynamicSharedMemorySize, SMEM5_BYTES);

    k1_proj<<<(N + 63) / 64, 256, SMEM1_BYTES>>>(h, wq, wk, msg_w1, msg_b1, N);
    k2_scores<<<1184, 256>>>(wt, tfreq, tphase, eidx, dts, E);
    k3_softmax<<<(E + 255) / 256, 256>>>(eidx, E);
    k4_edge<<<148, 256, SMEM4_BYTES>>>(ef, msg_w1 + H * H, msg_w2, msg_b2, eidx, E);
    k5_out<<<(N + 31) / 32, 256, SMEM5_BYTES>>>(h, wo, nw1, nb1, nw2, nb2,
                                                nw3, nb3, t_ptr, tfreq, tphase, out, N);
}

// round 6
// speedup vs baseline: 1.2289x; 1.2289x over previous
#include <cuda_runtime.h>
#include <cstdint>

#define H   128
#define ED  32
#define NH  4
#define DH  32
#define TD  32
#define MH  256

#define MAXN 50048
#define MAXE 640064

// ---------------- scratch (module-level device memory; no allocs) ----------
__device__ __align__(128) float    g_hq  [(size_t)MAXN * H];
__device__ __align__(128) float    g_hk  [(size_t)MAXN * H];
__device__ __align__(128) float    g_hm1 [(size_t)MAXN * H];   // h @ W1a + b1
__device__ __align__(128) float    g_scores[(size_t)MAXE * NH];
__device__ __align__(128) float    g_ex    [(size_t)MAXE * NH];
__device__ __align__(128) unsigned g_smax  [(size_t)MAXN * NH];
__device__ __align__(128) float    g_den   [(size_t)MAXN * NH];
__device__ __align__(128) float    g_agg   [(size_t)MAXN * H];

// ---------------- helpers ---------------------------------------------------
__device__ __forceinline__ unsigned enc_f(float f) {
    unsigned u = __float_as_uint(f);
    return (u & 0x80000000u) ? ~u : (u | 0x80000000u);
}
__device__ __forceinline__ float dec_f(unsigned k) {
    unsigned u = (k & 0x80000000u) ? (k & 0x7FFFFFFFu) : ~k;
    return __uint_as_float(u);
}
__device__ __forceinline__ float silu_f(float x) {
    return x / (1.0f + __expf(-x));
}
__device__ __forceinline__ void red_add_v4(float* p, float4 v) {
    asm volatile("red.global.add.v4.f32 [%0], {%1,%2,%3,%4};"
                 :: "l"(p), "f"(v.x), "f"(v.y), "f"(v.z), "f"(v.w) : "memory");
}
__device__ __forceinline__ void fma4(float4& acc, float a, const float4& b) {
    acc.x = fmaf(a, b.x, acc.x);
    acc.y = fmaf(a, b.y, acc.y);
    acc.z = fmaf(a, b.z, acc.z);
    acc.w = fmaf(a, b.w, acc.w);
}

// ============================================================================
// K1: node projections  hq = h@wq, hk = h@wk, hm1 = h@W1a + b1
// 64 rows/block, 8 rows/thread (8x weight reuse per strided LDS).
// ============================================================================
#define SMEM1_FLOATS (64 * H + 32 * H)
#define SMEM1_BYTES  (SMEM1_FLOATS * 4)

__global__ void __launch_bounds__(256) k1_proj(
    const float* __restrict__ h,
    const float* __restrict__ wq, const float* __restrict__ wk,
    const float* __restrict__ mw1, const float* __restrict__ mb1, int N)
{
    extern __shared__ float sm1[];
    float* sa = sm1;            // [64][128]
    float* sw = sm1 + 64 * H;   // [32][128]
    const int tid  = threadIdx.x;
    const int row0 = blockIdx.x * 64;

    for (int i = tid; i < 64 * H / 4; i += 256) {
        int r = i >> 5, c4 = i & 31;
        float4 v = make_float4(0.f, 0.f, 0.f, 0.f);
        if (row0 + r < N) v = ((const float4*)(h + (size_t)(row0 + r) * H))[c4];
        ((float4*)sa)[i] = v;
    }

    const int cg = tid & 31, rg = tid >> 5, c0 = cg << 2;

    #pragma unroll
    for (int m = 0; m < 3; m++) {
        const float* W = (m == 0) ? wq : (m == 1) ? wk : mw1;
        float4 acc[8];
        if (m == 2) {
            float4 b = ((const float4*)mb1)[cg];
            #pragma unroll
            for (int i = 0; i < 8; i++) acc[i] = b;
        } else {
            #pragma unroll
            for (int i = 0; i < 8; i++) acc[i] = make_float4(0.f, 0.f, 0.f, 0.f);
        }
        for (int ks = 0; ks < 4; ks++) {
            __syncthreads();
            for (int i = tid; i < 32 * H / 4; i += 256)
                ((float4*)sw)[i] = ((const float4*)(W + (size_t)ks * 32 * H))[i];
            __syncthreads();
            #pragma unroll
            for (int k4 = 0; k4 < 8; k4++) {
                float4 w0 = *(const float4*)&sw[(k4 * 4 + 0) * H + c0];
                float4 w1 = *(const float4*)&sw[(k4 * 4 + 1) * H + c0];
                float4 w2 = *(const float4*)&sw[(k4 * 4 + 2) * H + c0];
                float4 w3 = *(const float4*)&sw[(k4 * 4 + 3) * H + c0];
                #pragma unroll
                for (int i = 0; i < 8; i++) {
                    float4 a = *(const float4*)&sa[(rg * 8 + i) * H + ks * 32 + k4 * 4];
                    fma4(acc[i], a.x, w0); fma4(acc[i], a.y, w1);
                    fma4(acc[i], a.z, w2); fma4(acc[i], a.w, w3);
                }
            }
        }
        float* O = (m == 0) ? g_hq : (m == 1) ? g_hk : g_hm1;
        #pragma unroll
        for (int i = 0; i < 8; i++) {
            int r = rg * 8 + i;
            if (row0 + r < N)
                *(float4*)&O[(size_t)(row0 + r) * H + c0] = acc[i];
        }
    }
}

// ============================================================================
// K2: per-edge attention scores + segment max.
// 8 edges per warp as a mini-GEMM: strided wt loads reused 8x.
// ============================================================================
__global__ void __launch_bounds__(256) k2_scores(
    const float* __restrict__ wt,
    const float* __restrict__ tfreq, const float* __restrict__ tphase,
    const int* __restrict__ eidx, const float* __restrict__ dts, int E)
{
    __shared__ float swt[TD * H];
    __shared__ float sfreq[TD], sphase[TD];
    __shared__ __align__(16) float sdtf[8][8][TD];   // [warp][edge][td]
    const int tid = threadIdx.x;
    for (int i = tid; i < TD * H / 4; i += 256)
        ((float4*)swt)[i] = ((const float4*)wt)[i];
    if (tid < TD) { sfreq[tid] = tfreq[tid]; sphase[tid] = tphase[tid]; }
    __syncthreads();

    const int warp = tid >> 5, lane = tid & 31;
    const int c0 = lane << 2;
    const float fr = sfreq[lane], ph = sphase[lane];

    for (int base = (blockIdx.x * 8 + warp) * 8; base < E; base += gridDim.x * 64) {
        // lanes 0..7 hold edge meta
        int tgt_l = 0, src_l = 0; float dt_l = 0.f;
        if (lane < 8 && base + lane < E) {
            tgt_l = eidx[base + lane];
            src_l = eidx[E + base + lane];
            dt_l  = dts[base + lane];
        }
        const int nval = (E - base < 8) ? (E - base) : 8;

        #pragma unroll
        for (int j = 0; j < 8; j++) {
            float dtj = __shfl_sync(0xffffffffu, dt_l, j);
            sdtf[warp][j][lane] = cosf(dtj * fr + ph);
        }
        __syncwarp();

        float4 kv[8];
        #pragma unroll
        for (int j = 0; j < 8; j++) {
            int srcj = __shfl_sync(0xffffffffu, src_l, j);
            kv[j] = *(const float4*)&g_hk[(size_t)srcj * H + c0];
        }
        #pragma unroll
        for (int d4 = 0; d4 < 8; d4++) {
            float4 w0 = *(const float4*)&swt[(d4 * 4 + 0) * H + c0];
            float4 w1 = *(const float4*)&swt[(d4 * 4 + 1) * H + c0];
            float4 w2 = *(const float4*)&swt[(d4 * 4 + 2) * H + c0];
            float4 w3 = *(const float4*)&swt[(d4 * 4 + 3) * H + c0];
            #pragma unroll
            for (int j = 0; j < 8; j++) {
                float4 f = *(const float4*)&sdtf[warp][j][d4 * 4];
                fma4(kv[j], f.x, w0); fma4(kv[j], f.y, w1);
                fma4(kv[j], f.z, w2); fma4(kv[j], f.w, w3);
            }
        }
        #pragma unroll
        for (int j = 0; j < 8; j++) {
            int tgtj = __shfl_sync(0xffffffffu, tgt_l, j);
            float4 q4 = *(const float4*)&g_hq[(size_t)tgtj * H + c0];
            float p = q4.x * kv[j].x + q4.y * kv[j].y
                    + q4.z * kv[j].z + q4.w * kv[j].w;
            p += __shfl_xor_sync(0xffffffffu, p, 4);
            p += __shfl_xor_sync(0xffffffffu, p, 2);
            p += __shfl_xor_sync(0xffffffffu, p, 1);
            if ((lane & 7) == 0 && j < nval) {
                float s = p * 0.17677669529663687f;   // 1/sqrt(32)
                int hd = lane >> 3;
                g_scores[(size_t)(base + j) * NH + hd] = s;
                atomicMax(&g_smax[(size_t)tgtj * NH + hd], enc_f(s));
            }
        }
        __syncwarp();   // sdtf reads complete before next iteration's writes
    }
}

// ============================================================================
// K3: ex = exp(score - smax[tgt]); den[tgt] += ex
// ============================================================================
__global__ void __launch_bounds__(256) k3_softmax(
    const int* __restrict__ eidx, int E)
{
    int e = blockIdx.x * 256 + threadIdx.x;
    if (e >= E) return;
    int tgt = eidx[e];
    float4 s4 = *(const float4*)&g_scores[(size_t)e * NH];
    uint4  m4 = *(const uint4*)&g_smax[(size_t)tgt * NH];
    float4 v;
    v.x = __expf(s4.x - dec_f(m4.x));
    v.y = __expf(s4.y - dec_f(m4.y));
    v.z = __expf(s4.z - dec_f(m4.z));
    v.w = __expf(s4.w - dec_f(m4.w));
    *(float4*)&g_ex[(size_t)e * NH] = v;
    red_add_v4(&g_den[(size_t)tgt * NH], v);
}

// ============================================================================
// K4: edge message MLP + attention-weighted scatter.
// 512 threads, 128-edge tiles, 8 rows/thread (8x weight reuse, 16 warps/SM).
// ============================================================================
#define SMEM4_FLOATS (4096 + 16384 + 4096 + 16384 + 512 + 128)
#define SMEM4_BYTES  (SMEM4_FLOATS * 4)

__global__ void __launch_bounds__(512) k4_edge(
    const float* __restrict__ ef, const float* __restrict__ w1b,
    const float* __restrict__ w2, const float* __restrict__ b2,
    const int* __restrict__ eidx, int E)
{
    extern __shared__ float sm4[];
    float* sw1b = sm4;                 // [32][128]
    float* sw2  = sm4 + 4096;          // [128][128]
    float* sef  = sm4 + 20480;         // [128][32]
    float* shid = sm4 + 24576;         // [128][128]
    float* satt = sm4 + 40960;         // [128][4]
    int*   stgt = (int*)(sm4 + 41472); // [128]

    const int tid = threadIdx.x;
    for (int i = tid; i < 4096 / 4; i += 512)
        ((float4*)sw1b)[i] = ((const float4*)w1b)[i];
    for (int i = tid; i < 16384 / 4; i += 512)
        ((float4*)sw2)[i] = ((const float4*)w2)[i];

    const int cg = tid & 31, rg = tid >> 5, c0 = cg << 2, hd = cg >> 3;
    const float4 b2v = ((const float4*)b2)[cg];
    const int ntiles = (E + 127) >> 7;

    for (int tile = blockIdx.x; tile < ntiles; tile += gridDim.x) {
        const int e0 = tile << 7;
        __syncthreads();   // protect smem from previous tile (and weight load, tile 0)

        {   // attn + tgt for 128 edges (512 threads exactly cover 128x4)
            int r = tid >> 2, hh = tid & 3;
            int e = e0 + r;
            float a = 0.f; int tg = 0;
            if (e < E) {
                tg = eidx[e];
                a  = g_ex[(size_t)e * NH + hh] / g_den[(size_t)tg * NH + hh];
            }
            satt[r * 4 + hh] = a;
            if (hh == 0) stgt[r] = tg;
        }
        for (int i = tid; i < 4096 / 4; i += 512) {
            int r = i >> 3, c4 = i & 7;
            int e = e0 + r;
            float4 v = make_float4(0.f, 0.f, 0.f, 0.f);
            if (e < E) v = ((const float4*)(ef + (size_t)e * ED))[c4];
            ((float4*)sef)[i] = v;
        }
        __syncthreads();

        // phase A: pre-activation = hm1[src] + ef @ W1b, then silu -> shid
        float4 acc[8];
        #pragma unroll
        for (int i = 0; i < 8; i++) {
            int e = e0 + rg * 8 + i;
            int src = (e < E) ? eidx[E + e] : 0;
            acc[i] = *(const float4*)&g_hm1[(size_t)src * H + c0];
        }
        #pragma unroll
        for (int d4 = 0; d4 < 8; d4++) {
            float4 w0 = *(const float4*)&sw1b[(d4 * 4 + 0) * H + c0];
            float4 w1 = *(const float4*)&sw1b[(d4 * 4 + 1) * H + c0];
            float4 wz = *(const float4*)&sw1b[(d4 * 4 + 2) * H + c0];
            float4 w3 = *(const float4*)&sw1b[(d4 * 4 + 3) * H + c0];
            #pragma unroll
            for (int i = 0; i < 8; i++) {
                float4 a = *(const float4*)&sef[(rg * 8 + i) * ED + d4 * 4];
                fma4(acc[i], a.x, w0); fma4(acc[i], a.y, w1);
                fma4(acc[i], a.z, wz); fma4(acc[i], a.w, w3);
            }
        }
        #pragma unroll
        for (int i = 0; i < 8; i++) {
            float4 s;
            s.x = silu_f(acc[i].x); s.y = silu_f(acc[i].y);
            s.z = silu_f(acc[i].z); s.w = silu_f(acc[i].w);
            *(float4*)&shid[(rg * 8 + i) * H + c0] = s;
        }
        __syncthreads();

        // phase B: m = hid @ msg_w2 + b2  (8 rows/thread, weight reused 8x)
        float4 m4[8];
        #pragma unroll
        for (int i = 0; i < 8; i++) m4[i] = b2v;
        #pragma unroll 4
        for (int k4 = 0; k4 < 32; k4++) {
            float4 w0 = *(const float4*)&sw2[(k4 * 4 + 0) * H + c0];
            float4 w1 = *(const float4*)&sw2[(k4 * 4 + 1) * H + c0];
            float4 wz = *(const float4*)&sw2[(k4 * 4 + 2) * H + c0];
            float4 w3 = *(const float4*)&sw2[(k4 * 4 + 3) * H + c0];
            #pragma unroll
            for (int i = 0; i < 8; i++) {
                float4 a = *(const float4*)&shid[(rg * 8 + i) * H + k4 * 4];
                fma4(m4[i], a.x, w0); fma4(m4[i], a.y, w1);
                fma4(m4[i], a.z, wz); fma4(m4[i], a.w, w3);
            }
        }
        // phase C: scatter attn * m
        #pragma unroll
        for (int i = 0; i < 8; i++) {
            int r = rg * 8 + i, e = e0 + r;
            if (e < E) {
                float a  = satt[r * 4 + hd];
                int   tg = stgt[r];
                float4 v = make_float4(a * m4[i].x, a * m4[i].y,
                                       a * m4[i].z, a * m4[i].w);
                red_add_v4(&g_agg[(size_t)tg * H + c0], v);
            }
        }
    }
}

// ============================================================================
// K5: per-node output:  aggregated = agg@wo ; x=[h||aggregated||t_feat] ;
//     dh = (silu(silu(x@w1+b1)@w2+b2))@w3 + b3
// ============================================================================
#define SMEM5_FLOATS (9216 + 8192 + 8192)
#define SMEM5_BYTES  (SMEM5_FLOATS * 4)

__global__ void __launch_bounds__(256) k5_out(
    const float* __restrict__ h,  const float* __restrict__ wo,
    const float* __restrict__ w1, const float* __restrict__ b1,
    const float* __restrict__ w2, const float* __restrict__ b2,
    const float* __restrict__ w3, const float* __restrict__ b3,
    const float* __restrict__ tptr,
    const float* __restrict__ tfreq, const float* __restrict__ tphase,
    float* __restrict__ out, int N)
{
    extern __shared__ float sm5[];
    float* sx = sm5;                 // [32][288]
    float* sy = sm5 + 9216;          // [32][256]
    float* sw = sm5 + 9216 + 8192;   // up to [32][256]

    const int tid  = threadIdx.x;
    const int row0 = blockIdx.x * 32;
    const float t  = tptr[0];

    for (int i = tid; i < 32 * TD; i += 256) {
        int r = i >> 5, j = i & 31;
        sx[r * 288 + 256 + j] = cosf(t * tfreq[j] + tphase[j]);
    }
    for (int i = tid; i < 32 * H / 4; i += 256) {
        int r = i >> 5, c4 = i & 31;
        float4 v = make_float4(0.f, 0.f, 0.f, 0.f);
        if (row0 + r < N) v = ((const float4*)(h + (size_t)(row0 + r) * H))[c4];
        *(float4*)&sx[r * 288 + c4 * 4] = v;
    }
    for (int i = tid; i < 32 * H / 4; i += 256) {
        int r = i >> 5, c4 = i & 31;
        float4 v = make_float4(0.f, 0.f, 0.f, 0.f);
        if (row0 + r < N) v = ((const float4*)(g_agg + (size_t)(row0 + r) * H))[c4];
        ((float4*)sy)[i] = v;
    }
    __syncthreads();

    const int cg = tid & 31, rg = tid >> 5, c0 = cg << 2;

    // stage 0: aggregated = aggtile @ wo  -> sx[:, 128:256]
    {
        float4 acc[4];
        #pragma unroll
        for (int i = 0; i < 4; i++) acc[i] = make_float4(0.f, 0.f, 0.f, 0.f);
        for (int ks = 0; ks < 4; ks++) {
            __syncthreads();
            for (int i = tid; i < 32 * H / 4; i += 256)
                ((float4*)sw)[i] = ((const float4*)(wo + (size_t)ks * 32 * H))[i];
            __syncthreads();
            #pragma unroll
            for (int k4 = 0; k4 < 8; k4++) {
                float4 w0 = *(const float4*)&sw[(k4 * 4 + 0) * H + c0];
                float4 w1 = *(const float4*)&sw[(k4 * 4 + 1) * H + c0];
                float4 wz = *(const float4*)&sw[(k4 * 4 + 2) * H + c0];
                float4 w3 = *(const float4*)&sw[(k4 * 4 + 3) * H + c0];
                #pragma unroll
                for (int i = 0; i < 4; i++) {
                    float4 a = *(const float4*)&sy[(rg * 4 + i) * H + ks * 32 + k4 * 4];
                    fma4(acc[i], a.x, w0); fma4(acc[i], a.y, w1);
                    fma4(acc[i], a.z, wz); fma4(acc[i], a.w, w3);
                }
            }
        }
        __syncthreads();
        #pragma unroll
        for (int i = 0; i < 4; i++)
            *(float4*)&sx[(rg * 4 + i) * 288 + 128 + c0] = acc[i];
    }
    __syncthreads();

    const int cgB = tid & 63, rgB = tid >> 6, cB0 = cgB << 2;

    // stage 1: y1 = silu(x @ w1 + b1) -> sy [32][256]
    {
        float4 acc[8];
        float4 bb = ((const float4*)b1)[cgB];
        #pragma unroll
        for (int i = 0; i < 8; i++) acc[i] = bb;
        for (int ks = 0; ks < 9; ks++) {
            __syncthreads();
            for (int i = tid; i < 32 * MH / 4; i += 256)
                ((float4*)sw)[i] = ((const float4*)(w1 + (size_t)ks * 32 * MH))[i];
            __syncthreads();
            #pragma unroll
            for (int k4 = 0; k4 < 8; k4++) {
                float4 w0 = *(const float4*)&sw[(k4 * 4 + 0) * MH + cB0];
                float4 w1v = *(const float4*)&sw[(k4 * 4 + 1) * MH + cB0];
                float4 wz = *(const float4*)&sw[(k4 * 4 + 2) * MH + cB0];
                float4 w3 = *(const float4*)&sw[(k4 * 4 + 3) * MH + cB0];
                #pragma unroll
                for (int i = 0; i < 8; i++) {
                    float4 a = *(const float4*)&sx[(rgB * 8 + i) * 288 + ks * 32 + k4 * 4];
                    fma4(acc[i], a.x, w0); fma4(acc[i], a.y, w1v);
                    fma4(acc[i], a.z, wz); fma4(acc[i], a.w, w3);
                }
            }
        }
        __syncthreads();
        #pragma unroll
        for (int i = 0; i < 8; i++) {
            float4 s;
            s.x = silu_f(acc[i].x); s.y = silu_f(acc[i].y);
            s.z = silu_f(acc[i].z); s.w = silu_f(acc[i].w);
            *(float4*)&sy[(rgB * 8 + i) * MH + cB0] = s;
        }
    }
    __syncthreads();

    // stage 2: y2 = silu(y1 @ w2 + b2) -> sx rows (stride 288), cols 0:256
    {
        float4 acc[8];
        float4 bb = ((const float4*)b2)[cgB];
        #pragma unroll
        for (int i = 0; i < 8; i++) acc[i] = bb;
        for (int ks = 0; ks < 8; ks++) {
            __syncthreads();
            for (int i = tid; i < 32 * MH / 4; i += 256)
                ((float4*)sw)[i] = ((const float4*)(w2 + (size_t)ks * 32 * MH))[i];
            __syncthreads();
            #pragma unroll
            for (int k4 = 0; k4 < 8; k4++) {
                float4 w0 = *(const float4*)&sw[(k4 * 4 + 0) * MH + cB0];
                float4 w1v = *(const float4*)&sw[(k4 * 4 + 1) * MH + cB0];
                float4 wz = *(const float4*)&sw[(k4 * 4 + 2) * MH + cB0];
                float4 w3 = *(const float4*)&sw[(k4 * 4 + 3) * MH + cB0];
                #pragma unroll
                for (int i = 0; i < 8; i++) {
                    float4 a = *(const float4*)&sy[(rgB * 8 + i) * MH + ks * 32 + k4 * 4];
                    fma4(acc[i], a.x, w0); fma4(acc[i], a.y, w1v);
                    fma4(acc[i], a.z, wz); fma4(acc[i], a.w, w3);
                }
            }
        }
        __syncthreads();
        #pragma unroll
        for (int i = 0; i < 8; i++) {
            float4 s;
            s.x = silu_f(acc[i].x); s.y = silu_f(acc[i].y);
            s.z = silu_f(acc[i].z); s.w = silu_f(acc[i].w);
            *(float4*)&sx[(rgB * 8 + i) * 288 + cB0] = s;
        }
    }
    __syncthreads();

    // stage 3: out = y2 @ w3 + b3
    {
        float4 acc[4];
        float4 bb = ((const float4*)b3)[cg];
        #pragma unroll
        for (int i = 0; i < 4; i++) acc[i] = bb;
        for (int ks = 0; ks < 8; ks++) {
            __syncthreads();
            for (int i = tid; i < 32 * H / 4; i += 256)
                ((float4*)sw)[i] = ((const float4*)(w3 + (size_t)ks * 32 * H))[i];
            __syncthreads();
            #pragma unroll
            for (int k4 = 0; k4 < 8; k4++) {
                float4 w0 = *(const float4*)&sw[(k4 * 4 + 0) * H + c0];
                float4 w1v = *(const float4*)&sw[(k4 * 4 + 1) * H + c0];
                float4 wz = *(const float4*)&sw[(k4 * 4 + 2) * H + c0];
                float4 w3v = *(const float4*)&sw[(k4 * 4 + 3) * H + c0];
                #pragma unroll
                for (int i = 0; i < 4; i++) {
                    float4 a = *(const float4*)&sx[(rg * 4 + i) * 288 + ks * 32 + k4 * 4];
                    fma4(acc[i], a.x, w0); fma4(acc[i], a.y, w1v);
                    fma4(acc[i], a.z, wz); fma4(acc[i], a.w, w3v);
                }
            }
        }
        #pragma unroll
        for (int i = 0; i < 4; i++) {
            int r = rg * 4 + i;
            if (row0 + r < N)
                *(float4*)&out[(size_t)(row0 + r) * H + c0] = acc[i];
        }
    }
}

// ============================================================================
extern "C" void kernel_launch(void* const* d_in, const int* in_sizes, int n_in,
                              void* d_out, int out_size)
{
    int wbase = (in_sizes[5] == (H + ED) * H) ? 5 : 6;

    const float* t_ptr  = (const float*)d_in[0];
    const float* h      = (const float*)d_in[1];
    const int*   eidx   = (const int*)  d_in[2];
    const float* ef     = (const float*)d_in[3];
    const float* dts    = (const float*)d_in[4];
    const float* msg_w1 = (const float*)d_in[wbase + 0];
    const float* msg_b1 = (const float*)d_in[wbase + 1];
    const float* msg_w2 = (const float*)d_in[wbase + 2];
    const float* msg_b2 = (const float*)d_in[wbase + 3];
    const float* wq     = (const float*)d_in[wbase + 4];
    const float* wk     = (const float*)d_in[wbase + 5];
    const float* wt     = (const float*)d_in[wbase + 6];
    const float* wo     = (const float*)d_in[wbase + 7];
    const float* tfreq  = (const float*)d_in[wbase + 8];
    const float* tphase = (const float*)d_in[wbase + 9];
    const float* nw1    = (const float*)d_in[wbase + 10];
    const float* nb1    = (const float*)d_in[wbase + 11];
    const float* nw2    = (const float*)d_in[wbase + 12];
    const float* nb2    = (const float*)d_in[wbase + 13];
    const float* nw3    = (const float*)d_in[wbase + 14];
    const float* nb3    = (const float*)d_in[wbase + 15];
    float* out = (float*)d_out;

    const int N = in_sizes[1] / H;
    const int E = in_sizes[4];

    void *p_smax, *p_den, *p_agg;
    cudaGetSymbolAddress(&p_smax, g_smax);
    cudaGetSymbolAddress(&p_den,  g_den);
    cudaGetSymbolAddress(&p_agg,  g_agg);
    cudaMemsetAsync(p_smax, 0, (size_t)N * NH * sizeof(unsigned), 0);
    cudaMemsetAsync(p_den,  0, (size_t)N * NH * sizeof(float), 0);
    cudaMemsetAsync(p_agg,  0, (size_t)N * H  * sizeof(float), 0);

    cudaFuncSetAttribute(k1_proj, cudaFuncAttributeMaxDynamicSharedMemorySize, SMEM1_BYTES);
    cudaFuncSetAttribute(k4_edge, cudaFuncAttributeMaxDynamicSharedMemorySize, SMEM4_BYTES);
    cudaFuncSetAttribute(k5_out,  cudaFuncAttributeMaxDynamicSharedMemorySize, SMEM5_BYTES);

    k1_proj<<<(N + 63) / 64, 256, SMEM1_BYTES>>>(h, wq, wk, msg_w1, msg_b1, N);
    k2_scores<<<1184, 256>>>(wt, tfreq, tphase, eidx, dts, E);
    k3_softmax<<<(E + 255) / 256, 256>>>(eidx, E);
    k4_edge<<<148, 512, SMEM4_BYTES>>>(ef, msg_w1 + H * H, msg_w2, msg_b2, eidx, E);
    k5_out<<<(N + 31) / 32, 256, SMEM5_BYTES>>>(h, wo, nw1, nb1, nw2, nb2,
                                                nw3, nb3, t_ptr, tfreq, tphase, out, N);
}

// round 7
// speedup vs baseline: 1.2600x; 1.0253x over previous
#include <cuda_runtime.h>
#include <cstdint>

#define H   128
#define ED  32
#define NH  4
#define DH  32
#define TD  32
#define MH  256

#define MAXN 50048
#define MAXE 640064

typedef unsigned long long u64;

// ---------------- scratch (module-level device memory; no allocs) ----------
__device__ __align__(128) float    g_hq  [(size_t)MAXN * H];
__device__ __align__(128) float    g_hk  [(size_t)MAXN * H];
__device__ __align__(128) float    g_hm1 [(size_t)MAXN * H];   // h @ W1a + b1
__device__ __align__(128) float    g_scores[(size_t)MAXE * NH];
__device__ __align__(128) float    g_ex    [(size_t)MAXE * NH];
__device__ __align__(128) unsigned g_smax  [(size_t)MAXN * NH];
__device__ __align__(128) float    g_den   [(size_t)MAXN * NH];
__device__ __align__(128) float    g_agg   [(size_t)MAXN * H];

// ---------------- helpers ---------------------------------------------------
__device__ __forceinline__ unsigned enc_f(float f) {
    unsigned u = __float_as_uint(f);
    return (u & 0x80000000u) ? ~u : (u | 0x80000000u);
}
__device__ __forceinline__ float dec_f(unsigned k) {
    unsigned u = (k & 0x80000000u) ? (k & 0x7FFFFFFFu) : ~k;
    return __uint_as_float(u);
}
__device__ __forceinline__ float silu_f(float x) {
    return x / (1.0f + __expf(-x));
}
__device__ __forceinline__ void red_add_v4(float* p, float4 v) {
    asm volatile("red.global.add.v4.f32 [%0], {%1,%2,%3,%4};"
                 :: "l"(p), "f"(v.x), "f"(v.y), "f"(v.z), "f"(v.w) : "memory");
}
__device__ __forceinline__ void fma4(float4& acc, float a, const float4& b) {
    acc.x = fmaf(a, b.x, acc.x);
    acc.y = fmaf(a, b.y, acc.y);
    acc.z = fmaf(a, b.z, acc.z);
    acc.w = fmaf(a, b.w, acc.w);
}
// ---- packed f32x2 (Blackwell) ----
__device__ __forceinline__ u64 bc2(float a) {
    u64 r; asm("mov.b64 %0, {%1, %1};" : "=l"(r) : "f"(a)); return r;
}
__device__ __forceinline__ void fma2(u64& c, u64 a, u64 b) {
    asm("fma.rn.f32x2 %0, %1, %2, %0;" : "+l"(c) : "l"(a), "l"(b));
}
__device__ __forceinline__ float2 unpk(u64 v) {
    float2 f; asm("mov.b64 {%0, %1}, %2;" : "=f"(f.x), "=f"(f.y) : "l"(v)); return f;
}
// acc(.x=cols c0..c0+1, .y=cols c0+2..3) += a * w
__device__ __forceinline__ void fma4p(ulonglong2& acc, float a, const ulonglong2& w) {
    u64 aa = bc2(a);
    fma2(acc.x, aa, w.x);
    fma2(acc.y, aa, w.y);
}

// ============================================================================
// K1: node projections  hq = h@wq, hk = h@wk, hm1 = h@W1a + b1
// 64 rows/block, 8 rows/thread, packed f32x2 FMA.
// ============================================================================
#define SMEM1_FLOATS (64 * H + 32 * H)
#define SMEM1_BYTES  (SMEM1_FLOATS * 4)

__global__ void __launch_bounds__(256) k1_proj(
    const float* __restrict__ h,
    const float* __restrict__ wq, const float* __restrict__ wk,
    const float* __restrict__ mw1, const float* __restrict__ mb1, int N)
{
    extern __shared__ float sm1[];
    float* sa = sm1;            // [64][128]
    float* sw = sm1 + 64 * H;   // [32][128]
    const int tid  = threadIdx.x;
    const int row0 = blockIdx.x * 64;

    for (int i = tid; i < 64 * H / 4; i += 256) {
        int r = i >> 5, c4 = i & 31;
        float4 v = make_float4(0.f, 0.f, 0.f, 0.f);
        if (row0 + r < N) v = ((const float4*)(h + (size_t)(row0 + r) * H))[c4];
        ((float4*)sa)[i] = v;
    }

    const int cg = tid & 31, rg = tid >> 5, c0 = cg << 2;

    #pragma unroll
    for (int m = 0; m < 3; m++) {
        const float* W = (m == 0) ? wq : (m == 1) ? wk : mw1;
        ulonglong2 acc[8];
        if (m == 2) {
            ulonglong2 b = ((const ulonglong2*)mb1)[cg];
            #pragma unroll
            for (int i = 0; i < 8; i++) acc[i] = b;
        } else {
            #pragma unroll
            for (int i = 0; i < 8; i++) { acc[i].x = 0ull; acc[i].y = 0ull; }
        }
        for (int ks = 0; ks < 4; ks++) {
            __syncthreads();
            for (int i = tid; i < 32 * H / 4; i += 256)
                ((float4*)sw)[i] = ((const float4*)(W + (size_t)ks * 32 * H))[i];
            __syncthreads();
            #pragma unroll
            for (int k4 = 0; k4 < 8; k4++) {
                ulonglong2 w0 = *(const ulonglong2*)&sw[(k4 * 4 + 0) * H + c0];
                ulonglong2 w1 = *(const ulonglong2*)&sw[(k4 * 4 + 1) * H + c0];
                ulonglong2 w2 = *(const ulonglong2*)&sw[(k4 * 4 + 2) * H + c0];
                ulonglong2 w3 = *(const ulonglong2*)&sw[(k4 * 4 + 3) * H + c0];
                #pragma unroll
                for (int i = 0; i < 8; i++) {
                    float4 a = *(const float4*)&sa[(rg * 8 + i) * H + ks * 32 + k4 * 4];
                    fma4p(acc[i], a.x, w0); fma4p(acc[i], a.y, w1);
                    fma4p(acc[i], a.z, w2); fma4p(acc[i], a.w, w3);
                }
            }
        }
        float* O = (m == 0) ? g_hq : (m == 1) ? g_hk : g_hm1;
        #pragma unroll
        for (int i = 0; i < 8; i++) {
            int r = rg * 8 + i;
            if (row0 + r < N)
                *(ulonglong2*)&O[(size_t)(row0 + r) * H + c0] = acc[i];
        }
    }
}

// ============================================================================
// K2: per-edge attention scores + segment max.
// 8 edges per warp as a mini-GEMM: strided wt loads reused 8x.
// ============================================================================
__global__ void __launch_bounds__(256) k2_scores(
    const float* __restrict__ wt,
    const float* __restrict__ tfreq, const float* __restrict__ tphase,
    const int* __restrict__ eidx, const float* __restrict__ dts, int E)
{
    __shared__ float swt[TD * H];
    __shared__ float sfreq[TD], sphase[TD];
    __shared__ __align__(16) float sdtf[8][8][TD];   // [warp][edge][td]
    const int tid = threadIdx.x;
    for (int i = tid; i < TD * H / 4; i += 256)
        ((float4*)swt)[i] = ((const float4*)wt)[i];
    if (tid < TD) { sfreq[tid] = tfreq[tid]; sphase[tid] = tphase[tid]; }
    __syncthreads();

    const int warp = tid >> 5, lane = tid & 31;
    const int c0 = lane << 2;
    const float fr = sfreq[lane], ph = sphase[lane];

    for (int base = (blockIdx.x * 8 + warp) * 8; base < E; base += gridDim.x * 64) {
        int tgt_l = 0, src_l = 0; float dt_l = 0.f;
        if (lane < 8 && base + lane < E) {
            tgt_l = eidx[base + lane];
            src_l = eidx[E + base + lane];
            dt_l  = dts[base + lane];
        }
        const int nval = (E - base < 8) ? (E - base) : 8;

        #pragma unroll
        for (int j = 0; j < 8; j++) {
            float dtj = __shfl_sync(0xffffffffu, dt_l, j);
            sdtf[warp][j][lane] = cosf(dtj * fr + ph);
        }
        __syncwarp();

        float4 kv[8];
        #pragma unroll
        for (int j = 0; j < 8; j++) {
            int srcj = __shfl_sync(0xffffffffu, src_l, j);
            kv[j] = *(const float4*)&g_hk[(size_t)srcj * H + c0];
        }
        #pragma unroll
        for (int d4 = 0; d4 < 8; d4++) {
            float4 w0 = *(const float4*)&swt[(d4 * 4 + 0) * H + c0];
            float4 w1 = *(const float4*)&swt[(d4 * 4 + 1) * H + c0];
            float4 w2 = *(const float4*)&swt[(d4 * 4 + 2) * H + c0];
            float4 w3 = *(const float4*)&swt[(d4 * 4 + 3) * H + c0];
            #pragma unroll
            for (int j = 0; j < 8; j++) {
                float4 f = *(const float4*)&sdtf[warp][j][d4 * 4];
                fma4(kv[j], f.x, w0); fma4(kv[j], f.y, w1);
                fma4(kv[j], f.z, w2); fma4(kv[j], f.w, w3);
            }
        }
        #pragma unroll
        for (int j = 0; j < 8; j++) {
            int tgtj = __shfl_sync(0xffffffffu, tgt_l, j);
            float4 q4 = *(const float4*)&g_hq[(size_t)tgtj * H + c0];
            float p = q4.x * kv[j].x + q4.y * kv[j].y
                    + q4.z * kv[j].z + q4.w * kv[j].w;
            p += __shfl_xor_sync(0xffffffffu, p, 4);
            p += __shfl_xor_sync(0xffffffffu, p, 2);
            p += __shfl_xor_sync(0xffffffffu, p, 1);
            if ((lane & 7) == 0 && j < nval) {
                float s = p * 0.17677669529663687f;   // 1/sqrt(32)
                int hd = lane >> 3;
                g_scores[(size_t)(base + j) * NH + hd] = s;
                atomicMax(&g_smax[(size_t)tgtj * NH + hd], enc_f(s));
            }
        }
        __syncwarp();
    }
}

// ============================================================================
// K3: ex = exp(score - smax[tgt]); den[tgt] += ex
// ============================================================================
__global__ void __launch_bounds__(256) k3_softmax(
    const int* __restrict__ eidx, int E)
{
    int e = blockIdx.x * 256 + threadIdx.x;
    if (e >= E) return;
    int tgt = eidx[e];
    float4 s4 = *(const float4*)&g_scores[(size_t)e * NH];
    uint4  m4 = *(const uint4*)&g_smax[(size_t)tgt * NH];
    float4 v;
    v.x = __expf(s4.x - dec_f(m4.x));
    v.y = __expf(s4.y - dec_f(m4.y));
    v.z = __expf(s4.z - dec_f(m4.z));
    v.w = __expf(s4.w - dec_f(m4.w));
    *(float4*)&g_ex[(size_t)e * NH] = v;
    red_add_v4(&g_den[(size_t)tgt * NH], v);
}

// ============================================================================
// K4: edge message MLP + attention-weighted scatter.
// 512 threads, 128-edge tiles, 8 rows/thread, packed f32x2 FMA.
// ============================================================================
#define SMEM4_FLOATS (4096 + 16384 + 4096 + 16384 + 512 + 128)
#define SMEM4_BYTES  (SMEM4_FLOATS * 4)

__global__ void __launch_bounds__(512) k4_edge(
    const float* __restrict__ ef, const float* __restrict__ w1b,
    const float* __restrict__ w2, const float* __restrict__ b2,
    const int* __restrict__ eidx, int E)
{
    extern __shared__ float sm4[];
    float* sw1b = sm4;                 // [32][128]
    float* sw2  = sm4 + 4096;          // [128][128]
    float* sef  = sm4 + 20480;         // [128][32]
    float* shid = sm4 + 24576;         // [128][128]
    float* satt = sm4 + 40960;         // [128][4]
    int*   stgt = (int*)(sm4 + 41472); // [128]

    const int tid = threadIdx.x;
    for (int i = tid; i < 4096 / 4; i += 512)
        ((float4*)sw1b)[i] = ((const float4*)w1b)[i];
    for (int i = tid; i < 16384 / 4; i += 512)
        ((float4*)sw2)[i] = ((const float4*)w2)[i];

    const int cg = tid & 31, rg = tid >> 5, c0 = cg << 2, hd = cg >> 3;
    const ulonglong2 b2v = ((const ulonglong2*)b2)[cg];
    const int ntiles = (E + 127) >> 7;

    for (int tile = blockIdx.x; tile < ntiles; tile += gridDim.x) {
        const int e0 = tile << 7;
        __syncthreads();   // protect smem from previous tile (and weight load, tile 0)

        {   // attn + tgt for 128 edges (512 threads exactly cover 128x4)
            int r = tid >> 2, hh = tid & 3;
            int e = e0 + r;
            float a = 0.f; int tg = 0;
            if (e < E) {
                tg = eidx[e];
                a  = g_ex[(size_t)e * NH + hh] / g_den[(size_t)tg * NH + hh];
            }
            satt[r * 4 + hh] = a;
            if (hh == 0) stgt[r] = tg;
        }
        for (int i = tid; i < 4096 / 4; i += 512) {
            int r = i >> 3, c4 = i & 7;
            int e = e0 + r;
            float4 v = make_float4(0.f, 0.f, 0.f, 0.f);
            if (e < E) v = ((const float4*)(ef + (size_t)e * ED))[c4];
            ((float4*)sef)[i] = v;
        }
        __syncthreads();

        // phase A: pre-activation = hm1[src] + ef @ W1b, then silu -> shid
        ulonglong2 acc[8];
        #pragma unroll
        for (int i = 0; i < 8; i++) {
            int e = e0 + rg * 8 + i;
            int src = (e < E) ? eidx[E + e] : 0;
            acc[i] = *(const ulonglong2*)&g_hm1[(size_t)src * H + c0];
        }
        #pragma unroll
        for (int d4 = 0; d4 < 8; d4++) {
            ulonglong2 w0 = *(const ulonglong2*)&sw1b[(d4 * 4 + 0) * H + c0];
            ulonglong2 w1 = *(const ulonglong2*)&sw1b[(d4 * 4 + 1) * H + c0];
            ulonglong2 wz = *(const ulonglong2*)&sw1b[(d4 * 4 + 2) * H + c0];
            ulonglong2 w3 = *(const ulonglong2*)&sw1b[(d4 * 4 + 3) * H + c0];
            #pragma unroll
            for (int i = 0; i < 8; i++) {
                float4 a = *(const float4*)&sef[(rg * 8 + i) * ED + d4 * 4];
                fma4p(acc[i], a.x, w0); fma4p(acc[i], a.y, w1);
                fma4p(acc[i], a.z, wz); fma4p(acc[i], a.w, w3);
            }
        }
        #pragma unroll
        for (int i = 0; i < 8; i++) {
            float2 lo = unpk(acc[i].x), hi = unpk(acc[i].y);
            float4 s;
            s.x = silu_f(lo.x); s.y = silu_f(lo.y);
            s.z = silu_f(hi.x); s.w = silu_f(hi.y);
            *(float4*)&shid[(rg * 8 + i) * H + c0] = s;
        }
        __syncthreads();

        // phase B: m = hid @ msg_w2 + b2  (8 rows/thread, packed FMA)
        ulonglong2 m4[8];
        #pragma unroll
        for (int i = 0; i < 8; i++) m4[i] = b2v;
        #pragma unroll 4
        for (int k4 = 0; k4 < 32; k4++) {
            ulonglong2 w0 = *(const ulonglong2*)&sw2[(k4 * 4 + 0) * H + c0];
            ulonglong2 w1 = *(const ulonglong2*)&sw2[(k4 * 4 + 1) * H + c0];
            ulonglong2 wz = *(const ulonglong2*)&sw2[(k4 * 4 + 2) * H + c0];
            ulonglong2 w3 = *(const ulonglong2*)&sw2[(k4 * 4 + 3) * H + c0];
            #pragma unroll
            for (int i = 0; i < 8; i++) {
                float4 a = *(const float4*)&shid[(rg * 8 + i) * H + k4 * 4];
                fma4p(m4[i], a.x, w0); fma4p(m4[i], a.y, w1);
                fma4p(m4[i], a.z, wz); fma4p(m4[i], a.w, w3);
            }
        }
        // phase C: scatter attn * m
        #pragma unroll
        for (int i = 0; i < 8; i++) {
            int r = rg * 8 + i, e = e0 + r;
            if (e < E) {
                float a  = satt[r * 4 + hd];
                int   tg = stgt[r];
                float2 lo = unpk(m4[i].x), hi = unpk(m4[i].y);
                float4 v = make_float4(a * lo.x, a * lo.y, a * hi.x, a * hi.y);
                red_add_v4(&g_agg[(size_t)tg * H + c0], v);
            }
        }
    }
}

// ============================================================================
// K5: per-node output:  aggregated = agg@wo ; x=[h||aggregated||t_feat] ;
//     dh = (silu(silu(x@w1+b1)@w2+b2))@w3 + b3     -- packed f32x2 FMA
// ============================================================================
#define SMEM5_FLOATS (9216 + 8192 + 8192)
#define SMEM5_BYTES  (SMEM5_FLOATS * 4)

__global__ void __launch_bounds__(256) k5_out(
    const float* __restrict__ h,  const float* __restrict__ wo,
    const float* __restrict__ w1, const float* __restrict__ b1,
    const float* __restrict__ w2, const float* __restrict__ b2,
    const float* __restrict__ w3, const float* __restrict__ b3,
    const float* __restrict__ tptr,
    const float* __restrict__ tfreq, const float* __restrict__ tphase,
    float* __restrict__ out, int N)
{
    extern __shared__ float sm5[];
    float* sx = sm5;                 // [32][288]
    float* sy = sm5 + 9216;          // [32][256]
    float* sw = sm5 + 9216 + 8192;   // up to [32][256]

    const int tid  = threadIdx.x;
    const int row0 = blockIdx.x * 32;
    const float t  = tptr[0];

    for (int i = tid; i < 32 * TD; i += 256) {
        int r = i >> 5, j = i & 31;
        sx[r * 288 + 256 + j] = cosf(t * tfreq[j] + tphase[j]);
    }
    for (int i = tid; i < 32 * H / 4; i += 256) {
        int r = i >> 5, c4 = i & 31;
        float4 v = make_float4(0.f, 0.f, 0.f, 0.f);
        if (row0 + r < N) v = ((const float4*)(h + (size_t)(row0 + r) * H))[c4];
        *(float4*)&sx[r * 288 + c4 * 4] = v;
    }
    for (int i = tid; i < 32 * H / 4; i += 256) {
        int r = i >> 5, c4 = i & 31;
        float4 v = make_float4(0.f, 0.f, 0.f, 0.f);
        if (row0 + r < N) v = ((const float4*)(g_agg + (size_t)(row0 + r) * H))[c4];
        ((float4*)sy)[i] = v;
    }
    __syncthreads();

    const int cg = tid & 31, rg = tid >> 5, c0 = cg << 2;

    // stage 0: aggregated = aggtile @ wo  -> sx[:, 128:256]
    {
        ulonglong2 acc[4];
        #pragma unroll
        for (int i = 0; i < 4; i++) { acc[i].x = 0ull; acc[i].y = 0ull; }
        for (int ks = 0; ks < 4; ks++) {
            __syncthreads();
            for (int i = tid; i < 32 * H / 4; i += 256)
                ((float4*)sw)[i] = ((const float4*)(wo + (size_t)ks * 32 * H))[i];
            __syncthreads();
            #pragma unroll
            for (int k4 = 0; k4 < 8; k4++) {
                ulonglong2 w0 = *(const ulonglong2*)&sw[(k4 * 4 + 0) * H + c0];
                ulonglong2 w1 = *(const ulonglong2*)&sw[(k4 * 4 + 1) * H + c0];
                ulonglong2 wz = *(const ulonglong2*)&sw[(k4 * 4 + 2) * H + c0];
                ulonglong2 w3 = *(const ulonglong2*)&sw[(k4 * 4 + 3) * H + c0];
                #pragma unroll
                for (int i = 0; i < 4; i++) {
                    float4 a = *(const float4*)&sy[(rg * 4 + i) * H + ks * 32 + k4 * 4];
                    fma4p(acc[i], a.x, w0); fma4p(acc[i], a.y, w1);
                    fma4p(acc[i], a.z, wz); fma4p(acc[i], a.w, w3);
                }
            }
        }
        __syncthreads();
        #pragma unroll
        for (int i = 0; i < 4; i++)
            *(ulonglong2*)&sx[(rg * 4 + i) * 288 + 128 + c0] = acc[i];
    }
    __syncthreads();

    const int cgB = tid & 63, rgB = tid >> 6, cB0 = cgB << 2;

    // stage 1: y1 = silu(x @ w1 + b1) -> sy [32][256]
    {
        ulonglong2 acc[8];
        ulonglong2 bb = ((const ulonglong2*)b1)[cgB];
        #pragma unroll
        for (int i = 0; i < 8; i++) acc[i] = bb;
        for (int ks = 0; ks < 9; ks++) {
            __syncthreads();
            for (int i = tid; i < 32 * MH / 4; i += 256)
                ((float4*)sw)[i] = ((const float4*)(w1 + (size_t)ks * 32 * MH))[i];
            __syncthreads();
            #pragma unroll
            for (int k4 = 0; k4 < 8; k4++) {
                ulonglong2 w0 = *(const ulonglong2*)&sw[(k4 * 4 + 0) * MH + cB0];
                ulonglong2 w1v = *(const ulonglong2*)&sw[(k4 * 4 + 1) * MH + cB0];
                ulonglong2 wz = *(const ulonglong2*)&sw[(k4 * 4 + 2) * MH + cB0];
                ulonglong2 w3 = *(const ulonglong2*)&sw[(k4 * 4 + 3) * MH + cB0];
                #pragma unroll
                for (int i = 0; i < 8; i++) {
                    float4 a = *(const float4*)&sx[(rgB * 8 + i) * 288 + ks * 32 + k4 * 4];
                    fma4p(acc[i], a.x, w0); fma4p(acc[i], a.y, w1v);
                    fma4p(acc[i], a.z, wz); fma4p(acc[i], a.w, w3);
                }
            }
        }
        __syncthreads();
        #pragma unroll
        for (int i = 0; i < 8; i++) {
            float2 lo = unpk(acc[i].x), hi = unpk(acc[i].y);
            float4 s;
            s.x = silu_f(lo.x); s.y = silu_f(lo.y);
            s.z = silu_f(hi.x); s.w = silu_f(hi.y);
            *(float4*)&sy[(rgB * 8 + i) * MH + cB0] = s;
        }
    }
    __syncthreads();

    // stage 2: y2 = silu(y1 @ w2 + b2) -> sx rows (stride 288), cols 0:256
    {
        ulonglong2 acc[8];
        ulonglong2 bb = ((const ulonglong2*)b2)[cgB];
        #pragma unroll
        for (int i = 0; i < 8; i++) acc[i] = bb;
        for (int ks = 0; ks < 8; ks++) {
            __syncthreads();
            for (int i = tid; i < 32 * MH / 4; i += 256)
                ((float4*)sw)[i] = ((const float4*)(w2 + (size_t)ks * 32 * MH))[i];
            __syncthreads();
            #pragma unroll
            for (int k4 = 0; k4 < 8; k4++) {
                ulonglong2 w0 = *(const ulonglong2*)&sw[(k4 * 4 + 0) * MH + cB0];
                ulonglong2 w1v = *(const ulonglong2*)&sw[(k4 * 4 + 1) * MH + cB0];
                ulonglong2 wz = *(const ulonglong2*)&sw[(k4 * 4 + 2) * MH + cB0];
                ulonglong2 w3 = *(const ulonglong2*)&sw[(k4 * 4 + 3) * MH + cB0];
                #pragma unroll
                for (int i = 0; i < 8; i++) {
                    float4 a = *(const float4*)&sy[(rgB * 8 + i) * MH + ks * 32 + k4 * 4];
                    fma4p(acc[i], a.x, w0); fma4p(acc[i], a.y, w1v);
                    fma4p(acc[i], a.z, wz); fma4p(acc[i], a.w, w3);
                }
            }
        }
        __syncthreads();
        #pragma unroll
        for (int i = 0; i < 8; i++) {
            float2 lo = unpk(acc[i].x), hi = unpk(acc[i].y);
            float4 s;
            s.x = silu_f(lo.x); s.y = silu_f(lo.y);
            s.z = silu_f(hi.x); s.w = silu_f(hi.y);
            *(float4*)&sx[(rgB * 8 + i) * 288 + cB0] = s;
        }
    }
    __syncthreads();

    // stage 3: out = y2 @ w3 + b3
    {
        ulonglong2 acc[4];
        ulonglong2 bb = ((const ulonglong2*)b3)[cg];
        #pragma unroll
        for (int i = 0; i < 4; i++) acc[i] = bb;
        for (int ks = 0; ks < 8; ks++) {
            __syncthreads();
            for (int i = tid; i < 32 * H / 4; i += 256)
                ((float4*)sw)[i] = ((const float4*)(w3 + (size_t)ks * 32 * H))[i];
            __syncthreads();
            #pragma unroll
            for (int k4 = 0; k4 < 8; k4++) {
                ulonglong2 w0 = *(const ulonglong2*)&sw[(k4 * 4 + 0) * H + c0];
                ulonglong2 w1v = *(const ulonglong2*)&sw[(k4 * 4 + 1) * H + c0];
                ulonglong2 wz = *(const ulonglong2*)&sw[(k4 * 4 + 2) * H + c0];
                ulonglong2 w3v = *(const ulonglong2*)&sw[(k4 * 4 + 3) * H + c0];
                #pragma unroll
                for (int i = 0; i < 4; i++) {
                    float4 a = *(const float4*)&sx[(rg * 4 + i) * 288 + ks * 32 + k4 * 4];
                    fma4p(acc[i], a.x, w0); fma4p(acc[i], a.y, w1v);
                    fma4p(acc[i], a.z, wz); fma4p(acc[i], a.w, w3v);
                }
            }
        }
        #pragma unroll
        for (int i = 0; i < 4; i++) {
            int r = rg * 4 + i;
            if (row0 + r < N)
                *(ulonglong2*)&out[(size_t)(row0 + r) * H + c0] = acc[i];
        }
    }
}

// ============================================================================
extern "C" void kernel_launch(void* const* d_in, const int* in_sizes, int n_in,
                              void* d_out, int out_size)
{
    int wbase = (in_sizes[5] == (H + ED) * H) ? 5 : 6;

    const float* t_ptr  = (const float*)d_in[0];
    const float* h      = (const float*)d_in[1];
    const int*   eidx   = (const int*)  d_in[2];
    const float* ef     = (const float*)d_in[3];
    const float* dts    = (const float*)d_in[4];
    const float* msg_w1 = (const float*)d_in[wbase + 0];
    const float* msg_b1 = (const float*)d_in[wbase + 1];
    const float* msg_w2 = (const float*)d_in[wbase + 2];
    const float* msg_b2 = (const float*)d_in[wbase + 3];
    const float* wq     = (const float*)d_in[wbase + 4];
    const float* wk     = (const float*)d_in[wbase + 5];
    const float* wt     = (const float*)d_in[wbase + 6];
    const float* wo     = (const float*)d_in[wbase + 7];
    const float* tfreq  = (const float*)d_in[wbase + 8];
    const float* tphase = (const float*)d_in[wbase + 9];
    const float* nw1    = (const float*)d_in[wbase + 10];
    const float* nb1    = (const float*)d_in[wbase + 11];
    const float* nw2    = (const float*)d_in[wbase + 12];
    const float* nb2    = (const float*)d_in[wbase + 13];
    const float* nw3    = (const float*)d_in[wbase + 14];
    const float* nb3    = (const float*)d_in[wbase + 15];
    float* out = (float*)d_out;

    const int N = in_sizes[1] / H;
    const int E = in_sizes[4];

    void *p_smax, *p_den, *p_agg;
    cudaGetSymbolAddress(&p_smax, g_smax);
    cudaGetSymbolAddress(&p_den,  g_den);
    cudaGetSymbolAddress(&p_agg,  g_agg);
    cudaMemsetAsync(p_smax, 0, (size_t)N * NH * sizeof(unsigned), 0);
    cudaMemsetAsync(p_den,  0, (size_t)N * NH * sizeof(float), 0);
    cudaMemsetAsync(p_agg,  0, (size_t)N * H  * sizeof(float), 0);

    cudaFuncSetAttribute(k1_proj, cudaFuncAttributeMaxDynamicSharedMemorySize, SMEM1_BYTES);
    cudaFuncSetAttribute(k4_edge, cudaFuncAttributeMaxDynamicSharedMemorySize, SMEM4_BYTES);
    cudaFuncSetAttribute(k5_out,  cudaFuncAttributeMaxDynamicSharedMemorySize, SMEM5_BYTES);

    k1_proj<<<(N + 63) / 64, 256, SMEM1_BYTES>>>(h, wq, wk, msg_w1, msg_b1, N);
    k2_scores<<<1184, 256>>>(wt, tfreq, tphase, eidx, dts, E);
    k3_softmax<<<(E + 255) / 256, 256>>>(eidx, E);
    k4_edge<<<148, 512, SMEM4_BYTES>>>(ef, msg_w1 + H * H, msg_w2, msg_b2, eidx, E);
    k5_out<<<(N + 31) / 32, 256, SMEM5_BYTES>>>(h, wo, nw1, nb1, nw2, nb2,
                                                nw3, nb3, t_ptr, tfreq, tphase, out, N);
}

// round 11
// speedup vs baseline: 1.4327x; 1.1370x over previous
#include <cuda_runtime.h>
#include <cstdint>

#define H   128
#define ED  32
#define NH  4
#define DH  32
#define TD  32
#define MH  256

#define MAXN 50048
#define MAXE 640064

typedef unsigned long long u64;

// ---------------- scratch (module-level device memory; no allocs) ----------
__device__ __align__(128) float    g_hq  [(size_t)MAXN * H];
__device__ __align__(128) float    g_hk  [(size_t)MAXN * H];
__device__ __align__(128) float    g_hm1 [(size_t)MAXN * H];   // h @ W1a + b1
__device__ __align__(128) float    g_scores[(size_t)MAXE * NH];
__device__ __align__(128) float    g_ex    [(size_t)MAXE * NH];
__device__ __align__(128) unsigned g_smax  [(size_t)MAXN * NH];
__device__ __align__(128) float    g_den   [(size_t)MAXN * NH];
__device__ __align__(128) float    g_agg   [(size_t)MAXN * H];

// ---------------- helpers ---------------------------------------------------
__device__ __forceinline__ unsigned enc_f(float f) {
    unsigned u = __float_as_uint(f);
    return (u & 0x80000000u) ? ~u : (u | 0x80000000u);
}
__device__ __forceinline__ float dec_f(unsigned k) {
    unsigned u = (k & 0x80000000u) ? (k & 0x7FFFFFFFu) : ~k;
    return __uint_as_float(u);
}
__device__ __forceinline__ float silu_f(float x) {
    return x / (1.0f + __expf(-x));
}
__device__ __forceinline__ void red_add_v4(float* p, float4 v) {
    asm volatile("red.global.add.v4.f32 [%0], {%1,%2,%3,%4};"
                 :: "l"(p), "f"(v.x), "f"(v.y), "f"(v.z), "f"(v.w) : "memory");
}
__device__ __forceinline__ void red_add_v2(float* p, float x, float y) {
    asm volatile("red.global.add.v2.f32 [%0], {%1,%2};"
                 :: "l"(p), "f"(x), "f"(y) : "memory");
}
__device__ __forceinline__ void fma4(float4& acc, float a, const float4& b) {
    acc.x = fmaf(a, b.x, acc.x);
    acc.y = fmaf(a, b.y, acc.y);
    acc.z = fmaf(a, b.z, acc.z);
    acc.w = fmaf(a, b.w, acc.w);
}
// ---- packed f32x2 (k1/k5) ----
__device__ __forceinline__ u64 bc2(float a) {
    u64 r; asm("mov.b64 %0, {%1, %1};" : "=l"(r) : "f"(a)); return r;
}
__device__ __forceinline__ void fma2(u64& c, u64 a, u64 b) {
    asm("fma.rn.f32x2 %0, %1, %2, %0;" : "+l"(c) : "l"(a), "l"(b));
}
__device__ __forceinline__ float2 unpk(u64 v) {
    float2 f; asm("mov.b64 {%0, %1}, %2;" : "=f"(f.x), "=f"(f.y) : "l"(v)); return f;
}
__device__ __forceinline__ void fma4p(ulonglong2& acc, float a, const ulonglong2& w) {
    u64 aa = bc2(a);
    fma2(acc.x, aa, w.x);
    fma2(acc.y, aa, w.y);
}
// ---- bf16 pack / split ----
__device__ __forceinline__ uint32_t pk_bf16(float lo, float hi) {
    uint32_t r; asm("cvt.rn.bf16x2.f32 %0, %1, %2;" : "=r"(r) : "f"(hi), "f"(lo));
    return r;
}
__device__ __forceinline__ void split2(float x, float y, uint32_t& h, uint32_t& l) {
    h = pk_bf16(x, y);
    float xr = __uint_as_float((h & 0xFFFFu) << 16);
    float yr = __uint_as_float(h & 0xFFFF0000u);
    l = pk_bf16(x - xr, y - yr);
}
// ---- mma.sync bf16 m16n8k16 (legacy tensor path; valid on plain sm_100) ----
__device__ __forceinline__ void mma_bf16(float* c, const uint32_t* a,
                                         uint32_t b0, uint32_t b1) {
    asm volatile("mma.sync.aligned.m16n8k16.row.col.f32.bf16.bf16.f32 "
        "{%0,%1,%2,%3}, {%4,%5,%6,%7}, {%8,%9}, {%0,%1,%2,%3};"
        : "+f"(c[0]), "+f"(c[1]), "+f"(c[2]), "+f"(c[3])
        : "r"(a[0]), "r"(a[1]), "r"(a[2]), "r"(a[3]), "r"(b0), "r"(b1));
}

// ============================================================================
// K1: node projections (64 rows/block, 8 rows/thread, packed f32x2)
// ============================================================================
#define SMEM1_FLOATS (64 * H + 32 * H)
#define SMEM1_BYTES  (SMEM1_FLOATS * 4)

__global__ void __launch_bounds__(256) k1_proj(
    const float* __restrict__ h,
    const float* __restrict__ wq, const float* __restrict__ wk,
    const float* __restrict__ mw1, const float* __restrict__ mb1, int N)
{
    extern __shared__ float sm1[];
    float* sa = sm1;            // [64][128]
    float* sw = sm1 + 64 * H;   // [32][128]
    const int tid  = threadIdx.x;
    const int row0 = blockIdx.x * 64;

    for (int i = tid; i < 64 * H / 4; i += 256) {
        int r = i >> 5, c4 = i & 31;
        float4 v = make_float4(0.f, 0.f, 0.f, 0.f);
        if (row0 + r < N) v = ((const float4*)(h + (size_t)(row0 + r) * H))[c4];
        ((float4*)sa)[i] = v;
    }

    const int cg = tid & 31, rg = tid >> 5, c0 = cg << 2;

    #pragma unroll
    for (int m = 0; m < 3; m++) {
        const float* W = (m == 0) ? wq : (m == 1) ? wk : mw1;
        ulonglong2 acc[8];
        if (m == 2) {
            ulonglong2 b = ((const ulonglong2*)mb1)[cg];
            #pragma unroll
            for (int i = 0; i < 8; i++) acc[i] = b;
        } else {
            #pragma unroll
            for (int i = 0; i < 8; i++) { acc[i].x = 0ull; acc[i].y = 0ull; }
        }
        for (int ks = 0; ks < 4; ks++) {
            __syncthreads();
            for (int i = tid; i < 32 * H / 4; i += 256)
                ((float4*)sw)[i] = ((const float4*)(W + (size_t)ks * 32 * H))[i];
            __syncthreads();
            #pragma unroll
            for (int k4 = 0; k4 < 8; k4++) {
                ulonglong2 w0 = *(const ulonglong2*)&sw[(k4 * 4 + 0) * H + c0];
                ulonglong2 w1 = *(const ulonglong2*)&sw[(k4 * 4 + 1) * H + c0];
                ulonglong2 w2 = *(const ulonglong2*)&sw[(k4 * 4 + 2) * H + c0];
                ulonglong2 w3 = *(const ulonglong2*)&sw[(k4 * 4 + 3) * H + c0];
                #pragma unroll
                for (int i = 0; i < 8; i++) {
                    float4 a = *(const float4*)&sa[(rg * 8 + i) * H + ks * 32 + k4 * 4];
                    fma4p(acc[i], a.x, w0); fma4p(acc[i], a.y, w1);
                    fma4p(acc[i], a.z, w2); fma4p(acc[i], a.w, w3);
                }
            }
        }
        float* O = (m == 0) ? g_hq : (m == 1) ? g_hk : g_hm1;
        #pragma unroll
        for (int i = 0; i < 8; i++) {
            int r = rg * 8 + i;
            if (row0 + r < N)
                *(ulonglong2*)&O[(size_t)(row0 + r) * H + c0] = acc[i];
        }
    }
}

// ============================================================================
// K2: per-edge attention scores + segment max (8 edges/warp mini-GEMM)
// ============================================================================
__global__ void __launch_bounds__(256) k2_scores(
    const float* __restrict__ wt,
    const float* __restrict__ tfreq, const float* __restrict__ tphase,
    const int* __restrict__ eidx, const float* __restrict__ dts, int E)
{
    __shared__ float swt[TD * H];
    __shared__ float sfreq[TD], sphase[TD];
    __shared__ __align__(16) float sdtf[8][8][TD];
    const int tid = threadIdx.x;
    for (int i = tid; i < TD * H / 4; i += 256)
        ((float4*)swt)[i] = ((const float4*)wt)[i];
    if (tid < TD) { sfreq[tid] = tfreq[tid]; sphase[tid] = tphase[tid]; }
    __syncthreads();

    const int warp = tid >> 5, lane = tid & 31;
    const int c0 = lane << 2;
    const float fr = sfreq[lane], ph = sphase[lane];

    for (int base = (blockIdx.x * 8 + warp) * 8; base < E; base += gridDim.x * 64) {
        int tgt_l = 0, src_l = 0; float dt_l = 0.f;
        if (lane < 8 && base + lane < E) {
            tgt_l = eidx[base + lane];
            src_l = eidx[E + base + lane];
            dt_l  = dts[base + lane];
        }
        const int nval = (E - base < 8) ? (E - base) : 8;

        #pragma unroll
        for (int j = 0; j < 8; j++) {
            float dtj = __shfl_sync(0xffffffffu, dt_l, j);
            sdtf[warp][j][lane] = cosf(dtj * fr + ph);
        }
        __syncwarp();

        float4 kv[8];
        #pragma unroll
        for (int j = 0; j < 8; j++) {
            int srcj = __shfl_sync(0xffffffffu, src_l, j);
            kv[j] = *(const float4*)&g_hk[(size_t)srcj * H + c0];
        }
        #pragma unroll
        for (int d4 = 0; d4 < 8; d4++) {
            float4 w0 = *(const float4*)&swt[(d4 * 4 + 0) * H + c0];
            float4 w1 = *(const float4*)&swt[(d4 * 4 + 1) * H + c0];
            float4 w2 = *(const float4*)&swt[(d4 * 4 + 2) * H + c0];
            float4 w3 = *(const float4*)&swt[(d4 * 4 + 3) * H + c0];
            #pragma unroll
            for (int j = 0; j < 8; j++) {
                float4 f = *(const float4*)&sdtf[warp][j][d4 * 4];
                fma4(kv[j], f.x, w0); fma4(kv[j], f.y, w1);
                fma4(kv[j], f.z, w2); fma4(kv[j], f.w, w3);
            }
        }
        #pragma unroll
        for (int j = 0; j < 8; j++) {
            int tgtj = __shfl_sync(0xffffffffu, tgt_l, j);
            float4 q4 = *(const float4*)&g_hq[(size_t)tgtj * H + c0];
            float p = q4.x * kv[j].x + q4.y * kv[j].y
                    + q4.z * kv[j].z + q4.w * kv[j].w;
            p += __shfl_xor_sync(0xffffffffu, p, 4);
            p += __shfl_xor_sync(0xffffffffu, p, 2);
            p += __shfl_xor_sync(0xffffffffu, p, 1);
            if ((lane & 7) == 0 && j < nval) {
                float s = p * 0.17677669529663687f;
                int hd = lane >> 3;
                g_scores[(size_t)(base + j) * NH + hd] = s;
                atomicMax(&g_smax[(size_t)tgtj * NH + hd], enc_f(s));
            }
        }
        __syncwarp();
    }
}

// ============================================================================
// K3: ex = exp(score - smax[tgt]); den[tgt] += ex
// ============================================================================
__global__ void __launch_bounds__(256) k3_softmax(
    const int* __restrict__ eidx, int E)
{
    int e = blockIdx.x * 256 + threadIdx.x;
    if (e >= E) return;
    int tgt = eidx[e];
    float4 s4 = *(const float4*)&g_scores[(size_t)e * NH];
    uint4  m4 = *(const uint4*)&g_smax[(size_t)tgt * NH];
    float4 v;
    v.x = __expf(s4.x - dec_f(m4.x));
    v.y = __expf(s4.y - dec_f(m4.y));
    v.z = __expf(s4.z - dec_f(m4.z));
    v.w = __expf(s4.w - dec_f(m4.w));
    *(float4*)&g_ex[(size_t)e * NH] = v;
    red_add_v4(&g_den[(size_t)tgt * NH], v);
}

// ============================================================================
// K4: edge MLP + attention-weighted scatter.
// Phase A: hid = silu(hm1[src] + ef@W1b) scalar fp32 -> bf16 hi/lo pair.
// Phase B: hid@W2 via mma.sync bf16 m16n8k16, 3-term split (AhBh+AhBl+AlBh).
// Accumulators in registers; bias+attn fused into red.global.add.v2 scatter.
// 512 threads, 128-edge tiles, persistent, 1 block/SM.
//
// A tiles:  word layout [128 rows][68 words] (2 bf16/word, cols 0..127; stride
//           68 mod 32 == 4 -> fragment loads are perfectly bank-distinct).
// B tiles:  w2^T, word layout [64 k-pairs][136 words] (stride 136 mod 32 == 8).
// ============================================================================
#define AH_W   0
#define AL_W   8704
#define BH_W   17408
#define BL_W   26112
#define W1B_F  34816
#define EF_F   38912
#define ATT_F  43008
#define TGT_F  43520
#define SMEM4_WORDS 43648
#define SMEM4_BYTES (SMEM4_WORDS * 4)

__global__ void __launch_bounds__(512) k4_edge(
    const float* __restrict__ ef, const float* __restrict__ w1b,
    const float* __restrict__ w2, const float* __restrict__ b2,
    const int* __restrict__ eidx, int E)
{
    extern __shared__ float sm4[];
    uint32_t* AH = (uint32_t*)sm4 + AH_W;
    uint32_t* AL = (uint32_t*)sm4 + AL_W;
    uint32_t* BH = (uint32_t*)sm4 + BH_W;
    uint32_t* BL = (uint32_t*)sm4 + BL_W;
    float* sw1b = sm4 + W1B_F;
    float* sef  = sm4 + EF_F;
    float* satt = sm4 + ATT_F;
    int*   stgt = (int*)(sm4 + TGT_F);

    const int tid = threadIdx.x, wid = tid >> 5, lane = tid & 31;
    const int g = lane >> 2, t = lane & 3;

    // ---- one-time: B = w2^T split into bf16 hi/lo, k-pair-major layout ----
    for (int i = tid; i < H * H; i += 512) {
        int k = i >> 7, n = i & 127;
        float v = w2[(size_t)k * H + n];
        uint32_t ph = pk_bf16(v, 0.f);
        float vr = __uint_as_float((ph & 0xFFFFu) << 16);
        uint32_t pl = pk_bf16(v - vr, 0.f);
        int si = ((k >> 1) * 136 + n) * 2 + (k & 1);
        ((unsigned short*)BH)[si] = (unsigned short)(ph & 0xFFFFu);
        ((unsigned short*)BL)[si] = (unsigned short)(pl & 0xFFFFu);
    }
    for (int i = tid; i < 1024; i += 512)
        ((float4*)sw1b)[i] = ((const float4*)w1b)[i];

    // per-thread constants for the mma region
    const int m0 = (wid & 7) * 16;
    const int n0 = (wid >> 3) * 64;
    float2 bb[8];
    #pragma unroll
    for (int nt = 0; nt < 8; nt++)
        bb[nt] = *(const float2*)(b2 + n0 + nt * 8 + t * 2);

    const int c0 = lane << 2;
    const int ntiles = (E + 127) >> 7;

    for (int tile = blockIdx.x; tile < ntiles; tile += gridDim.x) {
        const int e0 = tile << 7;
        __syncthreads();   // previous tile fully consumed (also covers preload)

        {   // attn + tgt for 128 edges
            int r = tid >> 2, hh = tid & 3;
            int e = e0 + r;
            float a = 0.f; int tg = 0;
            if (e < E) {
                tg = eidx[e];
                a  = g_ex[(size_t)e * NH + hh] / g_den[(size_t)tg * NH + hh];
            }
            satt[r * 4 + hh] = a;
            if (hh == 0) stgt[r] = tg;
        }
        for (int i = tid; i < 1024; i += 512) {
            int r = i >> 3, c4 = i & 7;
            int e = e0 + r;
            float4 v = make_float4(0.f, 0.f, 0.f, 0.f);
            if (e < E) v = ((const float4*)(ef + (size_t)e * ED))[c4];
            ((float4*)sef)[i] = v;
        }
        __syncthreads();

        // phase A: hid = silu(hm1[src] + ef@W1b) -> bf16 hi/lo into AH/AL
        {
            float4 acc[8];
            #pragma unroll
            for (int i = 0; i < 8; i++) {
                int e = e0 + wid * 8 + i;
                int src = (e < E) ? eidx[E + e] : 0;
                acc[i] = *(const float4*)&g_hm1[(size_t)src * H + c0];
            }
            #pragma unroll
            for (int d4 = 0; d4 < 8; d4++) {
                float4 w0 = *(const float4*)&sw1b[(d4 * 4 + 0) * H + c0];
                float4 w1 = *(const float4*)&sw1b[(d4 * 4 + 1) * H + c0];
                float4 wz = *(const float4*)&sw1b[(d4 * 4 + 2) * H + c0];
                float4 w3 = *(const float4*)&sw1b[(d4 * 4 + 3) * H + c0];
                #pragma unroll
                for (int i = 0; i < 8; i++) {
                    float4 a = *(const float4*)&sef[(wid * 8 + i) * ED + d4 * 4];
                    fma4(acc[i], a.x, w0); fma4(acc[i], a.y, w1);
                    fma4(acc[i], a.z, wz); fma4(acc[i], a.w, w3);
                }
            }
            #pragma unroll
            for (int i = 0; i < 8; i++) {
                int row = wid * 8 + i;
                float sx = silu_f(acc[i].x), sy = silu_f(acc[i].y);
                float sz = silu_f(acc[i].z), sw = silu_f(acc[i].w);
                uint32_t h01, l01, h23, l23;
                split2(sx, sy, h01, l01);
                split2(sz, sw, h23, l23);
                int w0i = row * 68 + lane * 2;
                AH[w0i] = h01; AH[w0i + 1] = h23;
                AL[w0i] = l01; AL[w0i + 1] = l23;
            }
        }
        __syncthreads();

        // phase B: m = hid @ w2 via mma.sync bf16 (3-term split)
        float c[8][4];
        #pragma unroll
        for (int nt = 0; nt < 8; nt++)
            c[nt][0] = c[nt][1] = c[nt][2] = c[nt][3] = 0.f;

        #pragma unroll
        for (int kk = 0; kk < 8; kk++) {
            int ar0 = (m0 + g) * 68 + kk * 8 + t;
            int ar1 = (m0 + g + 8) * 68 + kk * 8 + t;
            uint32_t ah[4] = { AH[ar0], AH[ar1], AH[ar0 + 4], AH[ar1 + 4] };
            uint32_t al[4] = { AL[ar0], AL[ar1], AL[ar0 + 4], AL[ar1 + 4] };
            int br0 = (kk * 8 + t) * 136;
            int br1 = (kk * 8 + 4 + t) * 136;
            #pragma unroll
            for (int nt = 0; nt < 8; nt++) {
                int nn = n0 + nt * 8 + g;
                uint32_t bh0 = BH[br0 + nn], bh1 = BH[br1 + nn];
                uint32_t bl0 = BL[br0 + nn], bl1 = BL[br1 + nn];
                mma_bf16(c[nt], ah, bh0, bh1);
                mma_bf16(c[nt], ah, bl0, bl1);
                mma_bf16(c[nt], al, bh0, bh1);
            }
        }

        // scatter: agg[tgt] += attn * (m + b2)  (attn==0 for padded edges)
        {
            int r1 = m0 + g, r2 = r1 + 8;
            int tg1 = stgt[r1], tg2 = stgt[r2];
            int h0 = n0 >> 5;
            float a1h0 = satt[r1 * 4 + h0], a1h1 = satt[r1 * 4 + h0 + 1];
            float a2h0 = satt[r2 * 4 + h0], a2h1 = satt[r2 * 4 + h0 + 1];
            #pragma unroll
            for (int nt = 0; nt < 8; nt++) {
                float a1 = (nt < 4) ? a1h0 : a1h1;
                float a2 = (nt < 4) ? a2h0 : a2h1;
                int col0 = n0 + nt * 8 + t * 2;
                red_add_v2(&g_agg[(size_t)tg1 * H + col0],
                           a1 * (c[nt][0] + bb[nt].x), a1 * (c[nt][1] + bb[nt].y));
                red_add_v2(&g_agg[(size_t)tg2 * H + col0],
                           a2 * (c[nt][2] + bb[nt].x), a2 * (c[nt][3] + bb[nt].y));
            }
        }
    }
}

// ============================================================================
// K5: per-node output (packed f32x2 FMA)
// ============================================================================
#define SMEM5_FLOATS (9216 + 8192 + 8192)
#define SMEM5_BYTES  (SMEM5_FLOATS * 4)

__global__ void __launch_bounds__(256) k5_out(
    const float* __restrict__ h,  const float* __restrict__ wo,
    const float* __restrict__ w1, const float* __restrict__ b1,
    const float* __restrict__ w2, const float* __restrict__ b2,
    const float* __restrict__ w3, const float* __restrict__ b3,
    const float* __restrict__ tptr,
    const float* __restrict__ tfreq, const float* __restrict__ tphase,
    float* __restrict__ out, int N)
{
    extern __shared__ float sm5[];
    float* sx = sm5;                 // [32][288]
    float* sy = sm5 + 9216;          // [32][256]
    float* sw = sm5 + 9216 + 8192;   // up to [32][256]

    const int tid  = threadIdx.x;
    const int row0 = blockIdx.x * 32;
    const float t  = tptr[0];

    for (int i = tid; i < 32 * TD; i += 256) {
        int r = i >> 5, j = i & 31;
        sx[r * 288 + 256 + j] = cosf(t * tfreq[j] + tphase[j]);
    }
    for (int i = tid; i < 32 * H / 4; i += 256) {
        int r = i >> 5, c4 = i & 31;
        float4 v = make_float4(0.f, 0.f, 0.f, 0.f);
        if (row0 + r < N) v = ((const float4*)(h + (size_t)(row0 + r) * H))[c4];
        *(float4*)&sx[r * 288 + c4 * 4] = v;
    }
    for (int i = tid; i < 32 * H / 4; i += 256) {
        int r = i >> 5, c4 = i & 31;
        float4 v = make_float4(0.f, 0.f, 0.f, 0.f);
        if (row0 + r < N) v = ((const float4*)(g_agg + (size_t)(row0 + r) * H))[c4];
        ((float4*)sy)[i] = v;
    }
    __syncthreads();

    const int cg = tid & 31, rg = tid >> 5, c0 = cg << 2;

    // stage 0: aggregated = aggtile @ wo  -> sx[:, 128:256]
    {
        ulonglong2 acc[4];
        #pragma unroll
        for (int i = 0; i < 4; i++) { acc[i].x = 0ull; acc[i].y = 0ull; }
        for (int ks = 0; ks < 4; ks++) {
            __syncthreads();
            for (int i = tid; i < 32 * H / 4; i += 256)
                ((float4*)sw)[i] = ((const float4*)(wo + (size_t)ks * 32 * H))[i];
            __syncthreads();
            #pragma unroll
            for (int k4 = 0; k4 < 8; k4++) {
                ulonglong2 w0 = *(const ulonglong2*)&sw[(k4 * 4 + 0) * H + c0];
                ulonglong2 w1 = *(const ulonglong2*)&sw[(k4 * 4 + 1) * H + c0];
                ulonglong2 wz = *(const ulonglong2*)&sw[(k4 * 4 + 2) * H + c0];
                ulonglong2 w3 = *(const ulonglong2*)&sw[(k4 * 4 + 3) * H + c0];
                #pragma unroll
                for (int i = 0; i < 4; i++) {
                    float4 a = *(const float4*)&sy[(rg * 4 + i) * H + ks * 32 + k4 * 4];
                    fma4p(acc[i], a.x, w0); fma4p(acc[i], a.y, w1);
                    fma4p(acc[i], a.z, wz); fma4p(acc[i], a.w, w3);
                }
            }
        }
        __syncthreads();
        #pragma unroll
        for (int i = 0; i < 4; i++)
            *(ulonglong2*)&sx[(rg * 4 + i) * 288 + 128 + c0] = acc[i];
    }
    __syncthreads();

    const int cgB = tid & 63, rgB = tid >> 6, cB0 = cgB << 2;

    // stage 1: y1 = silu(x @ w1 + b1) -> sy [32][256]
    {
        ulonglong2 acc[8];
        ulonglong2 bb = ((const ulonglong2*)b1)[cgB];
        #pragma unroll
        for (int i = 0; i < 8; i++) acc[i] = bb;
        for (int ks = 0; ks < 9; ks++) {
            __syncthreads();
            for (int i = tid; i < 32 * MH / 4; i += 256)
                ((float4*)sw)[i] = ((const float4*)(w1 + (size_t)ks * 32 * MH))[i];
            __syncthreads();
            #pragma unroll
            for (int k4 = 0; k4 < 8; k4++) {
                ulonglong2 w0 = *(const ulonglong2*)&sw[(k4 * 4 + 0) * MH + cB0];
                ulonglong2 w1v = *(const ulonglong2*)&sw[(k4 * 4 + 1) * MH + cB0];
                ulonglong2 wz = *(const ulonglong2*)&sw[(k4 * 4 + 2) * MH + cB0];
                ulonglong2 w3 = *(const ulonglong2*)&sw[(k4 * 4 + 3) * MH + cB0];
                #pragma unroll
                for (int i = 0; i < 8; i++) {
                    float4 a = *(const float4*)&sx[(rgB * 8 + i) * 288 + ks * 32 + k4 * 4];
                    fma4p(acc[i], a.x, w0); fma4p(acc[i], a.y, w1v);
                    fma4p(acc[i], a.z, wz); fma4p(acc[i], a.w, w3);
                }
            }
        }
        __syncthreads();
        #pragma unroll
        for (int i = 0; i < 8; i++) {
            float2 lo = unpk(acc[i].x), hi = unpk(acc[i].y);
            float4 s;
            s.x = silu_f(lo.x); s.y = silu_f(lo.y);
            s.z = silu_f(hi.x); s.w = silu_f(hi.y);
            *(float4*)&sy[(rgB * 8 + i) * MH + cB0] = s;
        }
    }
    __syncthreads();

    // stage 2: y2 = silu(y1 @ w2 + b2) -> sx rows (stride 288), cols 0:256
    {
        ulonglong2 acc[8];
        ulonglong2 bb = ((const ulonglong2*)b2)[cgB];
        #pragma unroll
        for (int i = 0; i < 8; i++) acc[i] = bb;
        for (int ks = 0; ks < 8; ks++) {
            __syncthreads();
            for (int i = tid; i < 32 * MH / 4; i += 256)
                ((float4*)sw)[i] = ((const float4*)(w2 + (size_t)ks * 32 * MH))[i];
            __syncthreads();
            #pragma unroll
            for (int k4 = 0; k4 < 8; k4++) {
                ulonglong2 w0 = *(const ulonglong2*)&sw[(k4 * 4 + 0) * MH + cB0];
                ulonglong2 w1v = *(const ulonglong2*)&sw[(k4 * 4 + 1) * MH + cB0];
                ulonglong2 wz = *(const ulonglong2*)&sw[(k4 * 4 + 2) * MH + cB0];
                ulonglong2 w3 = *(const ulonglong2*)&sw[(k4 * 4 + 3) * MH + cB0];
                #pragma unroll
                for (int i = 0; i < 8; i++) {
                    float4 a = *(const float4*)&sy[(rgB * 8 + i) * MH + ks * 32 + k4 * 4];
                    fma4p(acc[i], a.x, w0); fma4p(acc[i], a.y, w1v);
                    fma4p(acc[i], a.z, wz); fma4p(acc[i], a.w, w3);
                }
            }
        }
        __syncthreads();
        #pragma unroll
        for (int i = 0; i < 8; i++) {
            float2 lo = unpk(acc[i].x), hi = unpk(acc[i].y);
            float4 s;
            s.x = silu_f(lo.x); s.y = silu_f(lo.y);
            s.z = silu_f(hi.x); s.w = silu_f(hi.y);
            *(float4*)&sx[(rgB * 8 + i) * 288 + cB0] = s;
        }
    }
    __syncthreads();

    // stage 3: out = y2 @ w3 + b3
    {
        ulonglong2 acc[4];
        ulonglong2 bb = ((const ulonglong2*)b3)[cg];
        #pragma unroll
        for (int i = 0; i < 4; i++) acc[i] = bb;
        for (int ks = 0; ks < 8; ks++) {
            __syncthreads();
            for (int i = tid; i < 32 * H / 4; i += 256)
                ((float4*)sw)[i] = ((const float4*)(w3 + (size_t)ks * 32 * H))[i];
            __syncthreads();
            #pragma unroll
            for (int k4 = 0; k4 < 8; k4++) {
                ulonglong2 w0 = *(const ulonglong2*)&sw[(k4 * 4 + 0) * H + c0];
                ulonglong2 w1v = *(const ulonglong2*)&sw[(k4 * 4 + 1) * H + c0];
                ulonglong2 wz = *(const ulonglong2*)&sw[(k4 * 4 + 2) * H + c0];
                ulonglong2 w3v = *(const ulonglong2*)&sw[(k4 * 4 + 3) * H + c0];
                #pragma unroll
                for (int i = 0; i < 4; i++) {
                    float4 a = *(const float4*)&sx[(rg * 4 + i) * 288 + ks * 32 + k4 * 4];
                    fma4p(acc[i], a.x, w0); fma4p(acc[i], a.y, w1v);
                    fma4p(acc[i], a.z, wz); fma4p(acc[i], a.w, w3v);
                }
            }
        }
        #pragma unroll
        for (int i = 0; i < 4; i++) {
            int r = rg * 4 + i;
            if (row0 + r < N)
                *(ulonglong2*)&out[(size_t)(row0 + r) * H + c0] = acc[i];
        }
    }
}

// ============================================================================
extern "C" void kernel_launch(void* const* d_in, const int* in_sizes, int n_in,
                              void* d_out, int out_size)
{
    int wbase = (in_sizes[5] == (H + ED) * H) ? 5 : 6;

    const float* t_ptr  = (const float*)d_in[0];
    const float* h      = (const float*)d_in[1];
    const int*   eidx   = (const int*)  d_in[2];
    const float* ef     = (const float*)d_in[3];
    const float* dts    = (const float*)d_in[4];
    const float* msg_w1 = (const float*)d_in[wbase + 0];
    const float* msg_b1 = (const float*)d_in[wbase + 1];
    const float* msg_w2 = (const float*)d_in[wbase + 2];
    const float* msg_b2 = (const float*)d_in[wbase + 3];
    const float* wq     = (const float*)d_in[wbase + 4];
    const float* wk     = (const float*)d_in[wbase + 5];
    const float* wt     = (const float*)d_in[wbase + 6];
    const float* wo     = (const float*)d_in[wbase + 7];
    const float* tfreq  = (const float*)d_in[wbase + 8];
    const float* tphase = (const float*)d_in[wbase + 9];
    const float* nw1    = (const float*)d_in[wbase + 10];
    const float* nb1    = (const float*)d_in[wbase + 11];
    const float* nw2    = (const float*)d_in[wbase + 12];
    const float* nb2    = (const float*)d_in[wbase + 13];
    const float* nw3    = (const float*)d_in[wbase + 14];
    const float* nb3    = (const float*)d_in[wbase + 15];
    float* out = (float*)d_out;

    const int N = in_sizes[1] / H;
    const int E = in_sizes[4];

    void *p_smax, *p_den, *p_agg;
    cudaGetSymbolAddress(&p_smax, g_smax);
    cudaGetSymbolAddress(&p_den,  g_den);
    cudaGetSymbolAddress(&p_agg,  g_agg);
    cudaMemsetAsync(p_smax, 0, (size_t)N * NH * sizeof(unsigned), 0);
    cudaMemsetAsync(p_den,  0, (size_t)N * NH * sizeof(float), 0);
    cudaMemsetAsync(p_agg,  0, (size_t)N * H  * sizeof(float), 0);

    cudaFuncSetAttribute(k1_proj, cudaFuncAttributeMaxDynamicSharedMemorySize, SMEM1_BYTES);
    cudaFuncSetAttribute(k4_edge, cudaFuncAttributeMaxDynamicSharedMemorySize, SMEM4_BYTES);
    cudaFuncSetAttribute(k5_out,  cudaFuncAttributeMaxDynamicSharedMemorySize, SMEM5_BYTES);

    k1_proj<<<(N + 63) / 64, 256, SMEM1_BYTES>>>(h, wq, wk, msg_w1, msg_b1, N);
    k2_scores<<<1184, 256>>>(wt, tfreq, tphase, eidx, dts, E);
    k3_softmax<<<(E + 255) / 256, 256>>>(eidx, E);
    k4_edge<<<148, 512, SMEM4_BYTES>>>(ef, msg_w1 + H * H, msg_w2, msg_b2, eidx, E);
    k5_out<<<(N + 31) / 32, 256, SMEM5_BYTES>>>(h, wo, nw1, nb1, nw2, nb2,
                                                nw3, nb3, t_ptr, tfreq, tphase, out, N);
}

// round 14
// speedup vs baseline: 1.5526x; 1.0837x over previous
#include <cuda_runtime.h>
#include <cstdint>

#define H   128
#define ED  32
#define NH  4
#define DH  32
#define TD  32
#define MH  256

#define MAXN 50048
#define MAXE 640064

typedef unsigned long long u64;

// ---------------- scratch (module-level device memory; no allocs) ----------
__device__ __align__(128) float    g_hq  [(size_t)MAXN * H];
__device__ __align__(128) float    g_hk  [(size_t)MAXN * H];
__device__ __align__(128) float    g_hm1 [(size_t)MAXN * H];   // h @ W1a + b1
__device__ __align__(128) float    g_scores[(size_t)MAXE * NH];
__device__ __align__(128) float    g_ex    [(size_t)MAXE * NH];
__device__ __align__(128) unsigned g_smax  [(size_t)MAXN * NH];
__device__ __align__(128) float    g_den   [(size_t)MAXN * NH];
__device__ __align__(128) float    g_agg   [(size_t)MAXN * H];

// ---------------- helpers ---------------------------------------------------
__device__ __forceinline__ unsigned enc_f(float f) {
    unsigned u = __float_as_uint(f);
    return (u & 0x80000000u) ? ~u : (u | 0x80000000u);
}
__device__ __forceinline__ float dec_f(unsigned k) {
    unsigned u = (k & 0x80000000u) ? (k & 0x7FFFFFFFu) : ~k;
    return __uint_as_float(u);
}
__device__ __forceinline__ float silu_f(float x) {
    return x / (1.0f + __expf(-x));
}
__device__ __forceinline__ void red_add_v4(float* p, float4 v) {
    asm volatile("red.global.add.v4.f32 [%0], {%1,%2,%3,%4};"
                 :: "l"(p), "f"(v.x), "f"(v.y), "f"(v.z), "f"(v.w) : "memory");
}
__device__ __forceinline__ void red_add_v2(float* p, float x, float y) {
    asm volatile("red.global.add.v2.f32 [%0], {%1,%2};"
                 :: "l"(p), "f"(x), "f"(y) : "memory");
}
__device__ __forceinline__ void fma4(float4& acc, float a, const float4& b) {
    acc.x = fmaf(a, b.x, acc.x);
    acc.y = fmaf(a, b.y, acc.y);
    acc.z = fmaf(a, b.z, acc.z);
    acc.w = fmaf(a, b.w, acc.w);
}
// ---- packed f32x2 (k1) ----
__device__ __forceinline__ u64 bc2(float a) {
    u64 r; asm("mov.b64 %0, {%1, %1};" : "=l"(r) : "f"(a)); return r;
}
__device__ __forceinline__ void fma2(u64& c, u64 a, u64 b) {
    asm("fma.rn.f32x2 %0, %1, %2, %0;" : "+l"(c) : "l"(a), "l"(b));
}
__device__ __forceinline__ float2 unpk(u64 v) {
    float2 f; asm("mov.b64 {%0, %1}, %2;" : "=f"(f.x), "=f"(f.y) : "l"(v)); return f;
}
__device__ __forceinline__ void fma4p(ulonglong2& acc, float a, const ulonglong2& w) {
    u64 aa = bc2(a);
    fma2(acc.x, aa, w.x);
    fma2(acc.y, aa, w.y);
}
// ---- bf16 pack / split ----
__device__ __forceinline__ uint32_t pk_bf16(float lo, float hi) {
    uint32_t r; asm("cvt.rn.bf16x2.f32 %0, %1, %2;" : "=r"(r) : "f"(hi), "f"(lo));
    return r;
}
__device__ __forceinline__ void split2(float x, float y, uint32_t& h, uint32_t& l) {
    h = pk_bf16(x, y);
    float xr = __uint_as_float((h & 0xFFFFu) << 16);
    float yr = __uint_as_float(h & 0xFFFF0000u);
    l = pk_bf16(x - xr, y - yr);
}
// ---- mma.sync bf16 m16n8k16 (legacy tensor path; valid on plain sm_100) ----
__device__ __forceinline__ void mma_bf16(float* c, const uint32_t* a,
                                         uint32_t b0, uint32_t b1) {
    asm volatile("mma.sync.aligned.m16n8k16.row.col.f32.bf16.bf16.f32 "
        "{%0,%1,%2,%3}, {%4,%5,%6,%7}, {%8,%9}, {%0,%1,%2,%3};"
        : "+f"(c[0]), "+f"(c[1]), "+f"(c[2]), "+f"(c[3])
        : "r"(a[0]), "r"(a[1]), "r"(a[2]), "r"(a[3]), "r"(b0), "r"(b1));
}

// ============================================================================
// K1: node projections (64 rows/block, 8 rows/thread, packed f32x2)
// ============================================================================
#define SMEM1_FLOATS (64 * H + 32 * H)
#define SMEM1_BYTES  (SMEM1_FLOATS * 4)

__global__ void __launch_bounds__(256) k1_proj(
    const float* __restrict__ h,
    const float* __restrict__ wq, const float* __restrict__ wk,
    const float* __restrict__ mw1, const float* __restrict__ mb1, int N)
{
    extern __shared__ float sm1[];
    float* sa = sm1;            // [64][128]
    float* sw = sm1 + 64 * H;   // [32][128]
    const int tid  = threadIdx.x;
    const int row0 = blockIdx.x * 64;

    for (int i = tid; i < 64 * H / 4; i += 256) {
        int r = i >> 5, c4 = i & 31;
        float4 v = make_float4(0.f, 0.f, 0.f, 0.f);
        if (row0 + r < N) v = ((const float4*)(h + (size_t)(row0 + r) * H))[c4];
        ((float4*)sa)[i] = v;
    }

    const int cg = tid & 31, rg = tid >> 5, c0 = cg << 2;

    #pragma unroll
    for (int m = 0; m < 3; m++) {
        const float* W = (m == 0) ? wq : (m == 1) ? wk : mw1;
        ulonglong2 acc[8];
        if (m == 2) {
            ulonglong2 b = ((const ulonglong2*)mb1)[cg];
            #pragma unroll
            for (int i = 0; i < 8; i++) acc[i] = b;
        } else {
            #pragma unroll
            for (int i = 0; i < 8; i++) { acc[i].x = 0ull; acc[i].y = 0ull; }
        }
        for (int ks = 0; ks < 4; ks++) {
            __syncthreads();
            for (int i = tid; i < 32 * H / 4; i += 256)
                ((float4*)sw)[i] = ((const float4*)(W + (size_t)ks * 32 * H))[i];
            __syncthreads();
            #pragma unroll
            for (int k4 = 0; k4 < 8; k4++) {
                ulonglong2 w0 = *(const ulonglong2*)&sw[(k4 * 4 + 0) * H + c0];
                ulonglong2 w1 = *(const ulonglong2*)&sw[(k4 * 4 + 1) * H + c0];
                ulonglong2 w2 = *(const ulonglong2*)&sw[(k4 * 4 + 2) * H + c0];
                ulonglong2 w3 = *(const ulonglong2*)&sw[(k4 * 4 + 3) * H + c0];
                #pragma unroll
                for (int i = 0; i < 8; i++) {
                    float4 a = *(const float4*)&sa[(rg * 8 + i) * H + ks * 32 + k4 * 4];
                    fma4p(acc[i], a.x, w0); fma4p(acc[i], a.y, w1);
                    fma4p(acc[i], a.z, w2); fma4p(acc[i], a.w, w3);
                }
            }
        }
        float* O = (m == 0) ? g_hq : (m == 1) ? g_hk : g_hm1;
        #pragma unroll
        for (int i = 0; i < 8; i++) {
            int r = rg * 8 + i;
            if (row0 + r < N)
                *(ulonglong2*)&O[(size_t)(row0 + r) * H + c0] = acc[i];
        }
    }
}

// ============================================================================
// K2: per-edge attention scores + segment max (8 edges/warp mini-GEMM)
// ============================================================================
__global__ void __launch_bounds__(256) k2_scores(
    const float* __restrict__ wt,
    const float* __restrict__ tfreq, const float* __restrict__ tphase,
    const int* __restrict__ eidx, const float* __restrict__ dts, int E)
{
    __shared__ float swt[TD * H];
    __shared__ float sfreq[TD], sphase[TD];
    __shared__ __align__(16) float sdtf[8][8][TD];
    const int tid = threadIdx.x;
    for (int i = tid; i < TD * H / 4; i += 256)
        ((float4*)swt)[i] = ((const float4*)wt)[i];
    if (tid < TD) { sfreq[tid] = tfreq[tid]; sphase[tid] = tphase[tid]; }
    __syncthreads();

    const int warp = tid >> 5, lane = tid & 31;
    const int c0 = lane << 2;
    const float fr = sfreq[lane], ph = sphase[lane];

    for (int base = (blockIdx.x * 8 + warp) * 8; base < E; base += gridDim.x * 64) {
        int tgt_l = 0, src_l = 0; float dt_l = 0.f;
        if (lane < 8 && base + lane < E) {
            tgt_l = eidx[base + lane];
            src_l = eidx[E + base + lane];
            dt_l  = dts[base + lane];
        }
        const int nval = (E - base < 8) ? (E - base) : 8;

        #pragma unroll
        for (int j = 0; j < 8; j++) {
            float dtj = __shfl_sync(0xffffffffu, dt_l, j);
            sdtf[warp][j][lane] = cosf(dtj * fr + ph);
        }
        __syncwarp();

        float4 kv[8];
        #pragma unroll
        for (int j = 0; j < 8; j++) {
            int srcj = __shfl_sync(0xffffffffu, src_l, j);
            kv[j] = *(const float4*)&g_hk[(size_t)srcj * H + c0];
        }
        #pragma unroll
        for (int d4 = 0; d4 < 8; d4++) {
            float4 w0 = *(const float4*)&swt[(d4 * 4 + 0) * H + c0];
            float4 w1 = *(const float4*)&swt[(d4 * 4 + 1) * H + c0];
            float4 w2 = *(const float4*)&swt[(d4 * 4 + 2) * H + c0];
            float4 w3 = *(const float4*)&swt[(d4 * 4 + 3) * H + c0];
            #pragma unroll
            for (int j = 0; j < 8; j++) {
                float4 f = *(const float4*)&sdtf[warp][j][d4 * 4];
                fma4(kv[j], f.x, w0); fma4(kv[j], f.y, w1);
                fma4(kv[j], f.z, w2); fma4(kv[j], f.w, w3);
            }
        }
        #pragma unroll
        for (int j = 0; j < 8; j++) {
            int tgtj = __shfl_sync(0xffffffffu, tgt_l, j);
            float4 q4 = *(const float4*)&g_hq[(size_t)tgtj * H + c0];
            float p = q4.x * kv[j].x + q4.y * kv[j].y
                    + q4.z * kv[j].z + q4.w * kv[j].w;
            p += __shfl_xor_sync(0xffffffffu, p, 4);
            p += __shfl_xor_sync(0xffffffffu, p, 2);
            p += __shfl_xor_sync(0xffffffffu, p, 1);
            if ((lane & 7) == 0 && j < nval) {
                float s = p * 0.17677669529663687f;
                int hd = lane >> 3;
                g_scores[(size_t)(base + j) * NH + hd] = s;
                atomicMax(&g_smax[(size_t)tgtj * NH + hd], enc_f(s));
            }
        }
        __syncwarp();
    }
}

// ============================================================================
// K3: ex = exp(score - smax[tgt]); den[tgt] += ex
// ============================================================================
__global__ void __launch_bounds__(256) k3_softmax(
    const int* __restrict__ eidx, int E)
{
    int e = blockIdx.x * 256 + threadIdx.x;
    if (e >= E) return;
    int tgt = eidx[e];
    float4 s4 = *(const float4*)&g_scores[(size_t)e * NH];
    uint4  m4 = *(const uint4*)&g_smax[(size_t)tgt * NH];
    float4 v;
    v.x = __expf(s4.x - dec_f(m4.x));
    v.y = __expf(s4.y - dec_f(m4.y));
    v.z = __expf(s4.z - dec_f(m4.z));
    v.w = __expf(s4.w - dec_f(m4.w));
    *(float4*)&g_ex[(size_t)e * NH] = v;
    red_add_v4(&g_den[(size_t)tgt * NH], v);
}

// ============================================================================
// K4: edge MLP + attention-weighted scatter (mma.sync bf16, 3-term split).
// Unchanged from R11 (verified WIN).
// ============================================================================
#define AH_W   0
#define AL_W   8704
#define BH_W   17408
#define BL_W   26112
#define W1B_F  34816
#define EF_F   38912
#define ATT_F  43008
#define TGT_F  43520
#define SMEM4_WORDS 43648
#define SMEM4_BYTES (SMEM4_WORDS * 4)

__global__ void __launch_bounds__(512) k4_edge(
    const float* __restrict__ ef, const float* __restrict__ w1b,
    const float* __restrict__ w2, const float* __restrict__ b2,
    const int* __restrict__ eidx, int E)
{
    extern __shared__ float sm4[];
    uint32_t* AH = (uint32_t*)sm4 + AH_W;
    uint32_t* AL = (uint32_t*)sm4 + AL_W;
    uint32_t* BH = (uint32_t*)sm4 + BH_W;
    uint32_t* BL = (uint32_t*)sm4 + BL_W;
    float* sw1b = sm4 + W1B_F;
    float* sef  = sm4 + EF_F;
    float* satt = sm4 + ATT_F;
    int*   stgt = (int*)(sm4 + TGT_F);

    const int tid = threadIdx.x, wid = tid >> 5, lane = tid & 31;
    const int g = lane >> 2, t = lane & 3;

    for (int i = tid; i < H * H; i += 512) {
        int k = i >> 7, n = i & 127;
        float v = w2[(size_t)k * H + n];
        uint32_t ph = pk_bf16(v, 0.f);
        float vr = __uint_as_float((ph & 0xFFFFu) << 16);
        uint32_t pl = pk_bf16(v - vr, 0.f);
        int si = ((k >> 1) * 136 + n) * 2 + (k & 1);
        ((unsigned short*)BH)[si] = (unsigned short)(ph & 0xFFFFu);
        ((unsigned short*)BL)[si] = (unsigned short)(pl & 0xFFFFu);
    }
    for (int i = tid; i < 1024; i += 512)
        ((float4*)sw1b)[i] = ((const float4*)w1b)[i];

    const int m0 = (wid & 7) * 16;
    const int n0 = (wid >> 3) * 64;
    float2 bb[8];
    #pragma unroll
    for (int nt = 0; nt < 8; nt++)
        bb[nt] = *(const float2*)(b2 + n0 + nt * 8 + t * 2);

    const int c0 = lane << 2;
    const int ntiles = (E + 127) >> 7;

    for (int tile = blockIdx.x; tile < ntiles; tile += gridDim.x) {
        const int e0 = tile << 7;
        __syncthreads();

        {
            int r = tid >> 2, hh = tid & 3;
            int e = e0 + r;
            float a = 0.f; int tg = 0;
            if (e < E) {
                tg = eidx[e];
                a  = g_ex[(size_t)e * NH + hh] / g_den[(size_t)tg * NH + hh];
            }
            satt[r * 4 + hh] = a;
            if (hh == 0) stgt[r] = tg;
        }
        for (int i = tid; i < 1024; i += 512) {
            int r = i >> 3, c4 = i & 7;
            int e = e0 + r;
            float4 v = make_float4(0.f, 0.f, 0.f, 0.f);
            if (e < E) v = ((const float4*)(ef + (size_t)e * ED))[c4];
            ((float4*)sef)[i] = v;
        }
        __syncthreads();

        {
            float4 acc[8];
            #pragma unroll
            for (int i = 0; i < 8; i++) {
                int e = e0 + wid * 8 + i;
                int src = (e < E) ? eidx[E + e] : 0;
                acc[i] = *(const float4*)&g_hm1[(size_t)src * H + c0];
            }
            #pragma unroll
            for (int d4 = 0; d4 < 8; d4++) {
                float4 w0 = *(const float4*)&sw1b[(d4 * 4 + 0) * H + c0];
                float4 w1 = *(const float4*)&sw1b[(d4 * 4 + 1) * H + c0];
                float4 wz = *(const float4*)&sw1b[(d4 * 4 + 2) * H + c0];
                float4 w3 = *(const float4*)&sw1b[(d4 * 4 + 3) * H + c0];
                #pragma unroll
                for (int i = 0; i < 8; i++) {
                    float4 a = *(const float4*)&sef[(wid * 8 + i) * ED + d4 * 4];
                    fma4(acc[i], a.x, w0); fma4(acc[i], a.y, w1);
                    fma4(acc[i], a.z, wz); fma4(acc[i], a.w, w3);
                }
            }
            #pragma unroll
            for (int i = 0; i < 8; i++) {
                int row = wid * 8 + i;
                float sx = silu_f(acc[i].x), sy = silu_f(acc[i].y);
                float sz = silu_f(acc[i].z), sw = silu_f(acc[i].w);
                uint32_t h01, l01, h23, l23;
                split2(sx, sy, h01, l01);
                split2(sz, sw, h23, l23);
                int w0i = row * 68 + lane * 2;
                AH[w0i] = h01; AH[w0i + 1] = h23;
                AL[w0i] = l01; AL[w0i + 1] = l23;
            }
        }
        __syncthreads();

        float c[8][4];
        #pragma unroll
        for (int nt = 0; nt < 8; nt++)
            c[nt][0] = c[nt][1] = c[nt][2] = c[nt][3] = 0.f;

        #pragma unroll
        for (int kk = 0; kk < 8; kk++) {
            int ar0 = (m0 + g) * 68 + kk * 8 + t;
            int ar1 = (m0 + g + 8) * 68 + kk * 8 + t;
            uint32_t ah[4] = { AH[ar0], AH[ar1], AH[ar0 + 4], AH[ar1 + 4] };
            uint32_t al[4] = { AL[ar0], AL[ar1], AL[ar0 + 4], AL[ar1 + 4] };
            int br0 = (kk * 8 + t) * 136;
            int br1 = (kk * 8 + 4 + t) * 136;
            #pragma unroll
            for (int nt = 0; nt < 8; nt++) {
                int nn = n0 + nt * 8 + g;
                uint32_t bh0 = BH[br0 + nn], bh1 = BH[br1 + nn];
                uint32_t bl0 = BL[br0 + nn], bl1 = BL[br1 + nn];
                mma_bf16(c[nt], ah, bh0, bh1);
                mma_bf16(c[nt], ah, bl0, bl1);
                mma_bf16(c[nt], al, bh0, bh1);
            }
        }

        {
            int r1 = m0 + g, r2 = r1 + 8;
            int tg1 = stgt[r1], tg2 = stgt[r2];
            int h0 = n0 >> 5;
            float a1h0 = satt[r1 * 4 + h0], a1h1 = satt[r1 * 4 + h0 + 1];
            float a2h0 = satt[r2 * 4 + h0], a2h1 = satt[r2 * 4 + h0 + 1];
            #pragma unroll
            for (int nt = 0; nt < 8; nt++) {
                float a1 = (nt < 4) ? a1h0 : a1h1;
                float a2 = (nt < 4) ? a2h0 : a2h1;
                int col0 = n0 + nt * 8 + t * 2;
                red_add_v2(&g_agg[(size_t)tg1 * H + col0],
                           a1 * (c[nt][0] + bb[nt].x), a1 * (c[nt][1] + bb[nt].y));
                red_add_v2(&g_agg[(size_t)tg2 * H + col0],
                           a2 * (c[nt][2] + bb[nt].x), a2 * (c[nt][3] + bb[nt].y));
            }
        }
    }
}

// ============================================================================
// K5: per-node output MLP on mma.sync bf16 (3-term split).
// 64 nodes/block, 512 threads.  X/Y activations in smem as bf16 hi/lo word
// pairs; B weights streamed per-32-k slab from gmem with in-place split.
// ============================================================================
#define XS 148
#define YS 132
#define K5_XH 0
#define K5_XL 9472
#define K5_YH 18944
#define K5_YL 27392
#define K5_B  35840
#define K5_BL 40064
#define SMEM5_WORDS 44288
#define SMEM5_BYTES (SMEM5_WORDS * 4)

__global__ void __launch_bounds__(512) k5_out(
    const float* __restrict__ h,  const float* __restrict__ wo,
    const float* __restrict__ w1, const float* __restrict__ b1,
    const float* __restrict__ w2, const float* __restrict__ b2,
    const float* __restrict__ w3, const float* __restrict__ b3,
    const float* __restrict__ tptr,
    const float* __restrict__ tfreq, const float* __restrict__ tphase,
    float* __restrict__ out, int N)
{
    extern __shared__ uint32_t sm5w[];
    uint32_t* XH = sm5w + K5_XH;
    uint32_t* XL = sm5w + K5_XL;
    uint32_t* YH = sm5w + K5_YH;
    uint32_t* YL = sm5w + K5_YL;
    uint32_t* BH = sm5w + K5_B;
    uint32_t* BL = sm5w + K5_BL;

    const int tid = threadIdx.x, wid = tid >> 5, lane = tid & 31;
    const int g = lane >> 2, t = lane & 3;
    const int row0 = blockIdx.x * 64;
    const float tval = tptr[0];

    // ---- build X (h cols 0..127, tfeat cols 256..287) and rawagg into Y ----
    for (int i = tid; i < 64 * 64; i += 512) {
        int r = i >> 6, wi = i & 63;
        float x = 0.f, y = 0.f;
        if (row0 + r < N) {
            float2 v = ((const float2*)(h + (size_t)(row0 + r) * H))[wi];
            x = v.x; y = v.y;
        }
        uint32_t hh, ll; split2(x, y, hh, ll);
        XH[r * XS + wi] = hh; XL[r * XS + wi] = ll;
    }
    for (int i = tid; i < 64 * 16; i += 512) {
        int r = i >> 4, wi = i & 15;
        float x = cosf(tval * tfreq[wi * 2]     + tphase[wi * 2]);
        float y = cosf(tval * tfreq[wi * 2 + 1] + tphase[wi * 2 + 1]);
        uint32_t hh, ll; split2(x, y, hh, ll);
        XH[r * XS + 128 + wi] = hh; XL[r * XS + 128 + wi] = ll;
    }
    for (int i = tid; i < 64 * 64; i += 512) {
        int r = i >> 6, wi = i & 63;
        float x = 0.f, y = 0.f;
        if (row0 + r < N) {
            float2 v = ((const float2*)(g_agg + (size_t)(row0 + r) * H))[wi];
            x = v.x; y = v.y;
        }
        uint32_t hh, ll; split2(x, y, hh, ll);
        YH[r * YS + wi] = hh; YL[r * YS + wi] = ll;
    }

    // ======================= stage 0: agg @ wo ==============================
    {
        const int m0 = (wid & 3) * 16, n0 = (wid >> 2) * 32;
        float c[4][4];
        #pragma unroll
        for (int nt = 0; nt < 4; nt++)
            c[nt][0] = c[nt][1] = c[nt][2] = c[nt][3] = 0.f;
        for (int ks = 0; ks < 4; ks++) {
            __syncthreads();
            for (int i = tid; i < 16 * 128; i += 512) {
                int kp = i >> 7, n = i & 127;
                int k0 = ks * 32 + kp * 2;
                float x = wo[(size_t)k0 * H + n];
                float y = wo[(size_t)(k0 + 1) * H + n];
                uint32_t hh, ll; split2(x, y, hh, ll);
                BH[kp * 136 + n] = hh; BL[kp * 136 + n] = ll;
            }
            __syncthreads();
            #pragma unroll
            for (int kk = 0; kk < 2; kk++) {
                int aw = ks * 16 + kk * 8 + t;
                int ar0 = (m0 + g) * YS + aw, ar1 = (m0 + g + 8) * YS + aw;
                uint32_t ah[4] = { YH[ar0], YH[ar1], YH[ar0 + 4], YH[ar1 + 4] };
                uint32_t al[4] = { YL[ar0], YL[ar1], YL[ar0 + 4], YL[ar1 + 4] };
                int br0 = (kk * 8 + t) * 136, br1 = (kk * 8 + 4 + t) * 136;
                #pragma unroll
                for (int nt = 0; nt < 4; nt++) {
                    int nn = n0 + nt * 8 + g;
                    uint32_t bh0 = BH[br0 + nn], bh1 = BH[br1 + nn];
                    uint32_t bl0 = BL[br0 + nn], bl1 = BL[br1 + nn];
                    mma_bf16(c[nt], ah, bh0, bh1);
                    mma_bf16(c[nt], ah, bl0, bl1);
                    mma_bf16(c[nt], al, bh0, bh1);
                }
            }
        }
        #pragma unroll
        for (int nt = 0; nt < 4; nt++) {
            int wi = 64 + (n0 >> 1) + nt * 4 + t;   // col 128 + n0 + nt*8 + t*2
            uint32_t hh, ll;
            split2(c[nt][0], c[nt][1], hh, ll);
            XH[(m0 + g) * XS + wi] = hh; XL[(m0 + g) * XS + wi] = ll;
            split2(c[nt][2], c[nt][3], hh, ll);
            XH[(m0 + g + 8) * XS + wi] = hh; XL[(m0 + g + 8) * XS + wi] = ll;
        }
    }

    // ======================= stage 1: X @ w1 + b1, silu =====================
    {
        const int m0 = (wid & 3) * 16, n0 = (wid >> 2) * 64;
        float c[8][4];
        #pragma unroll
        for (int nt = 0; nt < 8; nt++)
            c[nt][0] = c[nt][1] = c[nt][2] = c[nt][3] = 0.f;
        for (int ks = 0; ks < 9; ks++) {
            __syncthreads();
            for (int i = tid; i < 16 * 256; i += 512) {
                int kp = i >> 8, n = i & 255;
                int k0 = ks * 32 + kp * 2;
                float x = w1[(size_t)k0 * MH + n];
                float y = w1[(size_t)(k0 + 1) * MH + n];
                uint32_t hh, ll; split2(x, y, hh, ll);
                BH[kp * 264 + n] = hh; BL[kp * 264 + n] = ll;
            }
            __syncthreads();
            #pragma unroll
            for (int kk = 0; kk < 2; kk++) {
                int aw = ks * 16 + kk * 8 + t;
                int ar0 = (m0 + g) * XS + aw, ar1 = (m0 + g + 8) * XS + aw;
                uint32_t ah[4] = { XH[ar0], XH[ar1], XH[ar0 + 4], XH[ar1 + 4] };
                uint32_t al[4] = { XL[ar0], XL[ar1], XL[ar0 + 4], XL[ar1 + 4] };
                int br0 = (kk * 8 + t) * 264, br1 = (kk * 8 + 4 + t) * 264;
                #pragma unroll
                for (int nt = 0; nt < 8; nt++) {
                    int nn = n0 + nt * 8 + g;
                    uint32_t bh0 = BH[br0 + nn], bh1 = BH[br1 + nn];
                    uint32_t bl0 = BL[br0 + nn], bl1 = BL[br1 + nn];
                    mma_bf16(c[nt], ah, bh0, bh1);
                    mma_bf16(c[nt], ah, bl0, bl1);
                    mma_bf16(c[nt], al, bh0, bh1);
                }
            }
        }
        #pragma unroll
        for (int nt = 0; nt < 8; nt++) {
            int col = n0 + nt * 8 + t * 2;
            float bx = b1[col], by = b1[col + 1];
            int wi = col >> 1;
            uint32_t hh, ll;
            split2(silu_f(c[nt][0] + bx), silu_f(c[nt][1] + by), hh, ll);
            YH[(m0 + g) * YS + wi] = hh; YL[(m0 + g) * YS + wi] = ll;
            split2(silu_f(c[nt][2] + bx), silu_f(c[nt][3] + by), hh, ll);
            YH[(m0 + g + 8) * YS + wi] = hh; YL[(m0 + g + 8) * YS + wi] = ll;
        }
    }

    // ======================= stage 2: Y @ w2 + b2, silu =====================
    {
        const int m0 = (wid & 3) * 16, n0 = (wid >> 2) * 64;
        float c[8][4];
        #pragma unroll
        for (int nt = 0; nt < 8; nt++)
            c[nt][0] = c[nt][1] = c[nt][2] = c[nt][3] = 0.f;
        for (int ks = 0; ks < 8; ks++) {
            __syncthreads();
            for (int i = tid; i < 16 * 256; i += 512) {
                int kp = i >> 8, n = i & 255;
                int k0 = ks * 32 + kp * 2;
                float x = w2[(size_t)k0 * MH + n];
                float y = w2[(size_t)(k0 + 1) * MH + n];
                uint32_t hh, ll; split2(x, y, hh, ll);
                BH[kp * 264 + n] = hh; BL[kp * 264 + n] = ll;
            }
            __syncthreads();
            #pragma unroll
            for (int kk = 0; kk < 2; kk++) {
                int aw = ks * 16 + kk * 8 + t;
                int ar0 = (m0 + g) * YS + aw, ar1 = (m0 + g + 8) * YS + aw;
                uint32_t ah[4] = { YH[ar0], YH[ar1], YH[ar0 + 4], YH[ar1 + 4] };
                uint32_t al[4] = { YL[ar0], YL[ar1], YL[ar0 + 4], YL[ar1 + 4] };
                int br0 = (kk * 8 + t) * 264, br1 = (kk * 8 + 4 + t) * 264;
                #pragma unroll
                for (int nt = 0; nt < 8; nt++) {
                    int nn = n0 + nt * 8 + g;
                    uint32_t bh0 = BH[br0 + nn], bh1 = BH[br1 + nn];
                    uint32_t bl0 = BL[br0 + nn], bl1 = BL[br1 + nn];
                    mma_bf16(c[nt], ah, bh0, bh1);
                    mma_bf16(c[nt], ah, bl0, bl1);
                    mma_bf16(c[nt], al, bh0, bh1);
                }
            }
        }
        #pragma unroll
        for (int nt = 0; nt < 8; nt++) {
            int col = n0 + nt * 8 + t * 2;
            float bx = b2[col], by = b2[col + 1];
            int wi = col >> 1;
            uint32_t hh, ll;
            split2(silu_f(c[nt][0] + bx), silu_f(c[nt][1] + by), hh, ll);
            XH[(m0 + g) * XS + wi] = hh; XL[(m0 + g) * XS + wi] = ll;
            split2(silu_f(c[nt][2] + bx), silu_f(c[nt][3] + by), hh, ll);
            XH[(m0 + g + 8) * XS + wi] = hh; XL[(m0 + g + 8) * XS + wi] = ll;
        }
    }

    // ======================= stage 3: X @ w3 + b3 -> out ====================
    {
        const int m0 = (wid & 3) * 16, n0 = (wid >> 2) * 32;
        float c[4][4];
        #pragma unroll
        for (int nt = 0; nt < 4; nt++)
            c[nt][0] = c[nt][1] = c[nt][2] = c[nt][3] = 0.f;
        for (int ks = 0; ks < 8; ks++) {
            __syncthreads();
            for (int i = tid; i < 16 * 128; i += 512) {
                int kp = i >> 7, n = i & 127;
                int k0 = ks * 32 + kp * 2;
                float x = w3[(size_t)k0 * H + n];
                float y = w3[(size_t)(k0 + 1) * H + n];
                uint32_t hh, ll; split2(x, y, hh, ll);
                BH[kp * 136 + n] = hh; BL[kp * 136 + n] = ll;
            }
            __syncthreads();
            #pragma unroll
            for (int kk = 0; kk < 2; kk++) {
                int aw = ks * 16 + kk * 8 + t;
                int ar0 = (m0 + g) * XS + aw, ar1 = (m0 + g + 8) * XS + aw;
                uint32_t ah[4] = { XH[ar0], XH[ar1], XH[ar0 + 4], XH[ar1 + 4] };
                uint32_t al[4] = { XL[ar0], XL[ar1], XL[ar0 + 4], XL[ar1 + 4] };
                int br0 = (kk * 8 + t) * 136, br1 = (kk * 8 + 4 + t) * 136;
                #pragma unroll
                for (int nt = 0; nt < 4; nt++) {
                    int nn = n0 + nt * 8 + g;
                    uint32_t bh0 = BH[br0 + nn], bh1 = BH[br1 + nn];
                    uint32_t bl0 = BL[br0 + nn], bl1 = BL[br1 + nn];
                    mma_bf16(c[nt], ah, bh0, bh1);
                    mma_bf16(c[nt], ah, bl0, bl1);
                    mma_bf16(c[nt], al, bh0, bh1);
                }
            }
        }
        int r1 = row0 + m0 + g, r2 = r1 + 8;
        #pragma unroll
        for (int nt = 0; nt < 4; nt++) {
            int col = n0 + nt * 8 + t * 2;
            float bx = b3[col], by = b3[col + 1];
            if (r1 < N) {
                out[(size_t)r1 * H + col]     = c[nt][0] + bx;
                out[(size_t)r1 * H + col + 1] = c[nt][1] + by;
            }
            if (r2 < N) {
                out[(size_t)r2 * H + col]     = c[nt][2] + bx;
                out[(size_t)r2 * H + col + 1] = c[nt][3] + by;
            }
        }
    }
}

// ============================================================================
extern "C" void kernel_launch(void* const* d_in, const int* in_sizes, int n_in,
                              void* d_out, int out_size)
{
    int wbase = (in_sizes[5] == (H + ED) * H) ? 5 : 6;

    const float* t_ptr  = (const float*)d_in[0];
    const float* h      = (const float*)d_in[1];
    const int*   eidx   = (const int*)  d_in[2];
    const float* ef     = (const float*)d_in[3];
    const float* dts    = (const float*)d_in[4];
    const float* msg_w1 = (const float*)d_in[wbase + 0];
    const float* msg_b1 = (const float*)d_in[wbase + 1];
    const float* msg_w2 = (const float*)d_in[wbase + 2];
    const float* msg_b2 = (const float*)d_in[wbase + 3];
    const float* wq     = (const float*)d_in[wbase + 4];
    const float* wk     = (const float*)d_in[wbase + 5];
    const float* wt     = (const float*)d_in[wbase + 6];
    const float* wo     = (const float*)d_in[wbase + 7];
    const float* tfreq  = (const float*)d_in[wbase + 8];
    const float* tphase = (const float*)d_in[wbase + 9];
    const float* nw1    = (const float*)d_in[wbase + 10];
    const float* nb1    = (const float*)d_in[wbase + 11];
    const float* nw2    = (const float*)d_in[wbase + 12];
    const float* nb2    = (const float*)d_in[wbase + 13];
    const float* nw3    = (const float*)d_in[wbase + 14];
    const float* nb3    = (const float*)d_in[wbase + 15];
    float* out = (float*)d_out;

    const int N = in_sizes[1] / H;
    const int E = in_sizes[4];

    void *p_smax, *p_den, *p_agg;
    cudaGetSymbolAddress(&p_smax, g_smax);
    cudaGetSymbolAddress(&p_den,  g_den);
    cudaGetSymbolAddress(&p_agg,  g_agg);
    cudaMemsetAsync(p_smax, 0, (size_t)N * NH * sizeof(unsigned), 0);
    cudaMemsetAsync(p_den,  0, (size_t)N * NH * sizeof(float), 0);
    cudaMemsetAsync(p_agg,  0, (size_t)N * H  * sizeof(float), 0);

    cudaFuncSetAttribute(k1_proj, cudaFuncAttributeMaxDynamicSharedMemorySize, SMEM1_BYTES);
    cudaFuncSetAttribute(k4_edge, cudaFuncAttributeMaxDynamicSharedMemorySize, SMEM4_BYTES);
    cudaFuncSetAttribute(k5_out,  cudaFuncAttributeMaxDynamicSharedMemorySize, SMEM5_BYTES);

    k1_proj<<<(N + 63) / 64, 256, SMEM1_BYTES>>>(h, wq, wk, msg_w1, msg_b1, N);
    k2_scores<<<1184, 256>>>(wt, tfreq, tphase, eidx, dts, E);
    k3_softmax<<<(E + 255) / 256, 256>>>(eidx, E);
    k4_edge<<<148, 512, SMEM4_BYTES>>>(ef, msg_w1 + H * H, msg_w2, msg_b2, eidx, E);
    k5_out<<<(N + 63) / 64, 512, SMEM5_BYTES>>>(h, wo, nw1, nb1, nw2, nb2,
                                                nw3, nb3, t_ptr, tfreq, tphase, out, N);
}

// round 17
// speedup vs baseline: 1.6151x; 1.0402x over previous
#include <cuda_runtime.h>
#include <cstdint>

#define H   128
#define ED  32
#define NH  4
#define DH  32
#define TD  32
#define MH  256

#define MAXN 50048
#define MAXE 640064

typedef unsigned long long u64;

// ---------------- scratch (module-level device memory; no allocs) ----------
__device__ __align__(128) float    g_hq  [(size_t)MAXN * H];
__device__ __align__(128) float    g_hk  [(size_t)MAXN * H];
__device__ __align__(128) float    g_hm1 [(size_t)MAXN * H];   // h @ W1a + b1
__device__ __align__(128) float    g_scores[(size_t)MAXE * NH];
__device__ __align__(128) float    g_ex    [(size_t)MAXE * NH];
__device__ __align__(128) unsigned g_smax  [(size_t)MAXN * NH];
__device__ __align__(128) float    g_den   [(size_t)MAXN * NH];
__device__ __align__(128) float    g_agg   [(size_t)MAXN * H];

// ---------------- helpers ---------------------------------------------------
__device__ __forceinline__ unsigned enc_f(float f) {
    unsigned u = __float_as_uint(f);
    return (u & 0x80000000u) ? ~u : (u | 0x80000000u);
}
__device__ __forceinline__ float dec_f(unsigned k) {
    unsigned u = (k & 0x80000000u) ? (k & 0x7FFFFFFFu) : ~k;
    return __uint_as_float(u);
}
__device__ __forceinline__ float silu_f(float x) {
    return x / (1.0f + __expf(-x));
}
__device__ __forceinline__ void red_add_v4(float* p, float4 v) {
    asm volatile("red.global.add.v4.f32 [%0], {%1,%2,%3,%4};"
                 :: "l"(p), "f"(v.x), "f"(v.y), "f"(v.z), "f"(v.w) : "memory");
}
__device__ __forceinline__ void red_add_v2(float* p, float x, float y) {
    asm volatile("red.global.add.v2.f32 [%0], {%1,%2};"
                 :: "l"(p), "f"(x), "f"(y) : "memory");
}
__device__ __forceinline__ void fma4(float4& acc, float a, const float4& b) {
    acc.x = fmaf(a, b.x, acc.x);
    acc.y = fmaf(a, b.y, acc.y);
    acc.z = fmaf(a, b.z, acc.z);
    acc.w = fmaf(a, b.w, acc.w);
}
// ---- packed f32x2 (k1) ----
__device__ __forceinline__ u64 bc2(float a) {
    u64 r; asm("mov.b64 %0, {%1, %1};" : "=l"(r) : "f"(a)); return r;
}
__device__ __forceinline__ void fma2(u64& c, u64 a, u64 b) {
    asm("fma.rn.f32x2 %0, %1, %2, %0;" : "+l"(c) : "l"(a), "l"(b));
}
__device__ __forceinline__ float2 unpk(u64 v) {
    float2 f; asm("mov.b64 {%0, %1}, %2;" : "=f"(f.x), "=f"(f.y) : "l"(v)); return f;
}
__device__ __forceinline__ void fma4p(ulonglong2& acc, float a, const ulonglong2& w) {
    u64 aa = bc2(a);
    fma2(acc.x, aa, w.x);
    fma2(acc.y, aa, w.y);
}
// ---- bf16 pack / split ----
__device__ __forceinline__ uint32_t pk_bf16(float lo, float hi) {
    uint32_t r; asm("cvt.rn.bf16x2.f32 %0, %1, %2;" : "=r"(r) : "f"(hi), "f"(lo));
    return r;
}
__device__ __forceinline__ void split2(float x, float y, uint32_t& h, uint32_t& l) {
    h = pk_bf16(x, y);
    float xr = __uint_as_float((h & 0xFFFFu) << 16);
    float yr = __uint_as_float(h & 0xFFFF0000u);
    l = pk_bf16(x - xr, y - yr);
}
// ---- mma.sync bf16 m16n8k16 (legacy tensor path; valid on plain sm_100) ----
__device__ __forceinline__ void mma_bf16(float* c, const uint32_t* a,
                                         uint32_t b0, uint32_t b1) {
    asm volatile("mma.sync.aligned.m16n8k16.row.col.f32.bf16.bf16.f32 "
        "{%0,%1,%2,%3}, {%4,%5,%6,%7}, {%8,%9}, {%0,%1,%2,%3};"
        : "+f"(c[0]), "+f"(c[1]), "+f"(c[2]), "+f"(c[3])
        : "r"(a[0]), "r"(a[1]), "r"(a[2]), "r"(a[3]), "r"(b0), "r"(b1));
}

// ============================================================================
// K1: node projections (64 rows/block, 8 rows/thread, packed f32x2)
// ============================================================================
#define SMEM1_FLOATS (64 * H + 32 * H)
#define SMEM1_BYTES  (SMEM1_FLOATS * 4)

__global__ void __launch_bounds__(256) k1_proj(
    const float* __restrict__ h,
    const float* __restrict__ wq, const float* __restrict__ wk,
    const float* __restrict__ mw1, const float* __restrict__ mb1, int N)
{
    extern __shared__ float sm1[];
    float* sa = sm1;            // [64][128]
    float* sw = sm1 + 64 * H;   // [32][128]
    const int tid  = threadIdx.x;
    const int row0 = blockIdx.x * 64;

    for (int i = tid; i < 64 * H / 4; i += 256) {
        int r = i >> 5, c4 = i & 31;
        float4 v = make_float4(0.f, 0.f, 0.f, 0.f);
        if (row0 + r < N) v = ((const float4*)(h + (size_t)(row0 + r) * H))[c4];
        ((float4*)sa)[i] = v;
    }

    const int cg = tid & 31, rg = tid >> 5, c0 = cg << 2;

    #pragma unroll
    for (int m = 0; m < 3; m++) {
        const float* W = (m == 0) ? wq : (m == 1) ? wk : mw1;
        ulonglong2 acc[8];
        if (m == 2) {
            ulonglong2 b = ((const ulonglong2*)mb1)[cg];
            #pragma unroll
            for (int i = 0; i < 8; i++) acc[i] = b;
        } else {
            #pragma unroll
            for (int i = 0; i < 8; i++) { acc[i].x = 0ull; acc[i].y = 0ull; }
        }
        for (int ks = 0; ks < 4; ks++) {
            __syncthreads();
            for (int i = tid; i < 32 * H / 4; i += 256)
                ((float4*)sw)[i] = ((const float4*)(W + (size_t)ks * 32 * H))[i];
            __syncthreads();
            #pragma unroll
            for (int k4 = 0; k4 < 8; k4++) {
                ulonglong2 w0 = *(const ulonglong2*)&sw[(k4 * 4 + 0) * H + c0];
                ulonglong2 w1 = *(const ulonglong2*)&sw[(k4 * 4 + 1) * H + c0];
                ulonglong2 w2 = *(const ulonglong2*)&sw[(k4 * 4 + 2) * H + c0];
                ulonglong2 w3 = *(const ulonglong2*)&sw[(k4 * 4 + 3) * H + c0];
                #pragma unroll
                for (int i = 0; i < 8; i++) {
                    float4 a = *(const float4*)&sa[(rg * 8 + i) * H + ks * 32 + k4 * 4];
                    fma4p(acc[i], a.x, w0); fma4p(acc[i], a.y, w1);
                    fma4p(acc[i], a.z, w2); fma4p(acc[i], a.w, w3);
                }
            }
        }
        float* O = (m == 0) ? g_hq : (m == 1) ? g_hk : g_hm1;
        #pragma unroll
        for (int i = 0; i < 8; i++) {
            int r = rg * 8 + i;
            if (row0 + r < N)
                *(ulonglong2*)&O[(size_t)(row0 + r) * H + c0] = acc[i];
        }
    }
}

// ============================================================================
// K2: per-edge attention scores + segment max (8 edges/warp mini-GEMM)
// cos via MUFU __cosf (args small; err ~2^-21 << 1e-3 threshold)
// ============================================================================
__global__ void __launch_bounds__(256) k2_scores(
    const float* __restrict__ wt,
    const float* __restrict__ tfreq, const float* __restrict__ tphase,
    const int* __restrict__ eidx, const float* __restrict__ dts, int E)
{
    __shared__ float swt[TD * H];
    __shared__ float sfreq[TD], sphase[TD];
    __shared__ __align__(16) float sdtf[8][8][TD];
    const int tid = threadIdx.x;
    for (int i = tid; i < TD * H / 4; i += 256)
        ((float4*)swt)[i] = ((const float4*)wt)[i];
    if (tid < TD) { sfreq[tid] = tfreq[tid]; sphase[tid] = tphase[tid]; }
    __syncthreads();

    const int warp = tid >> 5, lane = tid & 31;
    const int c0 = lane << 2;
    const float fr = sfreq[lane], ph = sphase[lane];

    for (int base = (blockIdx.x * 8 + warp) * 8; base < E; base += gridDim.x * 64) {
        int tgt_l = 0, src_l = 0; float dt_l = 0.f;
        if (lane < 8 && base + lane < E) {
            tgt_l = eidx[base + lane];
            src_l = eidx[E + base + lane];
            dt_l  = dts[base + lane];
        }
        const int nval = (E - base < 8) ? (E - base) : 8;

        #pragma unroll
        for (int j = 0; j < 8; j++) {
            float dtj = __shfl_sync(0xffffffffu, dt_l, j);
            sdtf[warp][j][lane] = __cosf(fmaf(dtj, fr, ph));
        }
        __syncwarp();

        float4 kv[8];
        #pragma unroll
        for (int j = 0; j < 8; j++) {
            int srcj = __shfl_sync(0xffffffffu, src_l, j);
            kv[j] = *(const float4*)&g_hk[(size_t)srcj * H + c0];
        }
        #pragma unroll
        for (int d4 = 0; d4 < 8; d4++) {
            float4 w0 = *(const float4*)&swt[(d4 * 4 + 0) * H + c0];
            float4 w1 = *(const float4*)&swt[(d4 * 4 + 1) * H + c0];
            float4 w2 = *(const float4*)&swt[(d4 * 4 + 2) * H + c0];
            float4 w3 = *(const float4*)&swt[(d4 * 4 + 3) * H + c0];
            #pragma unroll
            for (int j = 0; j < 8; j++) {
                float4 f = *(const float4*)&sdtf[warp][j][d4 * 4];
                fma4(kv[j], f.x, w0); fma4(kv[j], f.y, w1);
                fma4(kv[j], f.z, w2); fma4(kv[j], f.w, w3);
            }
        }
        #pragma unroll
        for (int j = 0; j < 8; j++) {
            int tgtj = __shfl_sync(0xffffffffu, tgt_l, j);
            float4 q4 = *(const float4*)&g_hq[(size_t)tgtj * H + c0];
            float p = q4.x * kv[j].x + q4.y * kv[j].y
                    + q4.z * kv[j].z + q4.w * kv[j].w;
            p += __shfl_xor_sync(0xffffffffu, p, 4);
            p += __shfl_xor_sync(0xffffffffu, p, 2);
            p += __shfl_xor_sync(0xffffffffu, p, 1);
            if ((lane & 7) == 0 && j < nval) {
                float s = p * 0.17677669529663687f;
                int hd = lane >> 3;
                g_scores[(size_t)(base + j) * NH + hd] = s;
                atomicMax(&g_smax[(size_t)tgtj * NH + hd], enc_f(s));
            }
        }
        __syncwarp();
    }
}

// ============================================================================
// K3: ex = exp(score - smax[tgt]); den[tgt] += ex
// ============================================================================
__global__ void __launch_bounds__(256) k3_softmax(
    const int* __restrict__ eidx, int E)
{
    int e = blockIdx.x * 256 + threadIdx.x;
    if (e >= E) return;
    int tgt = eidx[e];
    float4 s4 = *(const float4*)&g_scores[(size_t)e * NH];
    uint4  m4 = *(const uint4*)&g_smax[(size_t)tgt * NH];
    float4 v;
    v.x = __expf(s4.x - dec_f(m4.x));
    v.y = __expf(s4.y - dec_f(m4.y));
    v.z = __expf(s4.z - dec_f(m4.z));
    v.w = __expf(s4.w - dec_f(m4.w));
    *(float4*)&g_ex[(size_t)e * NH] = v;
    red_add_v4(&g_den[(size_t)tgt * NH], v);
}

// ============================================================================
// K4: edge MLP + attention-weighted scatter (mma.sync bf16, 3-term split).
// Unchanged from R11 (verified WIN).
// ============================================================================
#define AH_W   0
#define AL_W   8704
#define BH_W   17408
#define BL_W   26112
#define W1B_F  34816
#define EF_F   38912
#define ATT_F  43008
#define TGT_F  43520
#define SMEM4_WORDS 43648
#define SMEM4_BYTES (SMEM4_WORDS * 4)

__global__ void __launch_bounds__(512) k4_edge(
    const float* __restrict__ ef, const float* __restrict__ w1b,
    const float* __restrict__ w2, const float* __restrict__ b2,
    const int* __restrict__ eidx, int E)
{
    extern __shared__ float sm4[];
    uint32_t* AH = (uint32_t*)sm4 + AH_W;
    uint32_t* AL = (uint32_t*)sm4 + AL_W;
    uint32_t* BH = (uint32_t*)sm4 + BH_W;
    uint32_t* BL = (uint32_t*)sm4 + BL_W;
    float* sw1b = sm4 + W1B_F;
    float* sef  = sm4 + EF_F;
    float* satt = sm4 + ATT_F;
    int*   stgt = (int*)(sm4 + TGT_F);

    const int tid = threadIdx.x, wid = tid >> 5, lane = tid & 31;
    const int g = lane >> 2, t = lane & 3;

    for (int i = tid; i < H * H; i += 512) {
        int k = i >> 7, n = i & 127;
        float v = w2[(size_t)k * H + n];
        uint32_t ph = pk_bf16(v, 0.f);
        float vr = __uint_as_float((ph & 0xFFFFu) << 16);
        uint32_t pl = pk_bf16(v - vr, 0.f);
        int si = ((k >> 1) * 136 + n) * 2 + (k & 1);
        ((unsigned short*)BH)[si] = (unsigned short)(ph & 0xFFFFu);
        ((unsigned short*)BL)[si] = (unsigned short)(pl & 0xFFFFu);
    }
    for (int i = tid; i < 1024; i += 512)
        ((float4*)sw1b)[i] = ((const float4*)w1b)[i];

    const int m0 = (wid & 7) * 16;
    const int n0 = (wid >> 3) * 64;
    float2 bb[8];
    #pragma unroll
    for (int nt = 0; nt < 8; nt++)
        bb[nt] = *(const float2*)(b2 + n0 + nt * 8 + t * 2);

    const int c0 = lane << 2;
    const int ntiles = (E + 127) >> 7;

    for (int tile = blockIdx.x; tile < ntiles; tile += gridDim.x) {
        const int e0 = tile << 7;
        __syncthreads();

        {
            int r = tid >> 2, hh = tid & 3;
            int e = e0 + r;
            float a = 0.f; int tg = 0;
            if (e < E) {
                tg = eidx[e];
                a  = g_ex[(size_t)e * NH + hh] / g_den[(size_t)tg * NH + hh];
            }
            satt[r * 4 + hh] = a;
            if (hh == 0) stgt[r] = tg;
        }
        for (int i = tid; i < 1024; i += 512) {
            int r = i >> 3, c4 = i & 7;
            int e = e0 + r;
            float4 v = make_float4(0.f, 0.f, 0.f, 0.f);
            if (e < E) v = ((const float4*)(ef + (size_t)e * ED))[c4];
            ((float4*)sef)[i] = v;
        }
        __syncthreads();

        {
            float4 acc[8];
            #pragma unroll
            for (int i = 0; i < 8; i++) {
                int e = e0 + wid * 8 + i;
                int src = (e < E) ? eidx[E + e] : 0;
                acc[i] = *(const float4*)&g_hm1[(size_t)src * H + c0];
            }
            #pragma unroll
            for (int d4 = 0; d4 < 8; d4++) {
                float4 w0 = *(const float4*)&sw1b[(d4 * 4 + 0) * H + c0];
                float4 w1 = *(const float4*)&sw1b[(d4 * 4 + 1) * H + c0];
                float4 wz = *(const float4*)&sw1b[(d4 * 4 + 2) * H + c0];
                float4 w3 = *(const float4*)&sw1b[(d4 * 4 + 3) * H + c0];
                #pragma unroll
                for (int i = 0; i < 8; i++) {
                    float4 a = *(const float4*)&sef[(wid * 8 + i) * ED + d4 * 4];
                    fma4(acc[i], a.x, w0); fma4(acc[i], a.y, w1);
                    fma4(acc[i], a.z, wz); fma4(acc[i], a.w, w3);
                }
            }
            #pragma unroll
            for (int i = 0; i < 8; i++) {
                int row = wid * 8 + i;
                float sx = silu_f(acc[i].x), sy = silu_f(acc[i].y);
                float sz = silu_f(acc[i].z), sw = silu_f(acc[i].w);
                uint32_t h01, l01, h23, l23;
                split2(sx, sy, h01, l01);
                split2(sz, sw, h23, l23);
                int w0i = row * 68 + lane * 2;
                AH[w0i] = h01; AH[w0i + 1] = h23;
                AL[w0i] = l01; AL[w0i + 1] = l23;
            }
        }
        __syncthreads();

        float c[8][4];
        #pragma unroll
        for (int nt = 0; nt < 8; nt++)
            c[nt][0] = c[nt][1] = c[nt][2] = c[nt][3] = 0.f;

        #pragma unroll
        for (int kk = 0; kk < 8; kk++) {
            int ar0 = (m0 + g) * 68 + kk * 8 + t;
            int ar1 = (m0 + g + 8) * 68 + kk * 8 + t;
            uint32_t ah[4] = { AH[ar0], AH[ar1], AH[ar0 + 4], AH[ar1 + 4] };
            uint32_t al[4] = { AL[ar0], AL[ar1], AL[ar0 + 4], AL[ar1 + 4] };
            int br0 = (kk * 8 + t) * 136;
            int br1 = (kk * 8 + 4 + t) * 136;
            #pragma unroll
            for (int nt = 0; nt < 8; nt++) {
                int nn = n0 + nt * 8 + g;
                uint32_t bh0 = BH[br0 + nn], bh1 = BH[br1 + nn];
                uint32_t bl0 = BL[br0 + nn], bl1 = BL[br1 + nn];
                mma_bf16(c[nt], ah, bh0, bh1);
                mma_bf16(c[nt], ah, bl0, bl1);
                mma_bf16(c[nt], al, bh0, bh1);
            }
        }

        {
            int r1 = m0 + g, r2 = r1 + 8;
            int tg1 = stgt[r1], tg2 = stgt[r2];
            int h0 = n0 >> 5;
            float a1h0 = satt[r1 * 4 + h0], a1h1 = satt[r1 * 4 + h0 + 1];
            float a2h0 = satt[r2 * 4 + h0], a2h1 = satt[r2 * 4 + h0 + 1];
            #pragma unroll
            for (int nt = 0; nt < 8; nt++) {
                float a1 = (nt < 4) ? a1h0 : a1h1;
                float a2 = (nt < 4) ? a2h0 : a2h1;
                int col0 = n0 + nt * 8 + t * 2;
                red_add_v2(&g_agg[(size_t)tg1 * H + col0],
                           a1 * (c[nt][0] + bb[nt].x), a1 * (c[nt][1] + bb[nt].y));
                red_add_v2(&g_agg[(size_t)tg2 * H + col0],
                           a2 * (c[nt][2] + bb[nt].x), a2 * (c[nt][3] + bb[nt].y));
            }
        }
    }
}

// ============================================================================
// K5: per-node output MLP on mma.sync bf16 (3-term split). As R14, cos->MUFU.
// ============================================================================
#define XS 148
#define YS 132
#define K5_XH 0
#define K5_XL 9472
#define K5_YH 18944
#define K5_YL 27392
#define K5_B  35840
#define K5_BL 40064
#define SMEM5_WORDS 44288
#define SMEM5_BYTES (SMEM5_WORDS * 4)

__global__ void __launch_bounds__(512) k5_out(
    const float* __restrict__ h,  const float* __restrict__ wo,
    const float* __restrict__ w1, const float* __restrict__ b1,
    const float* __restrict__ w2, const float* __restrict__ b2,
    const float* __restrict__ w3, const float* __restrict__ b3,
    const float* __restrict__ tptr,
    const float* __restrict__ tfreq, const float* __restrict__ tphase,
    float* __restrict__ out, int N)
{
    extern __shared__ uint32_t sm5w[];
    uint32_t* XH = sm5w + K5_XH;
    uint32_t* XL = sm5w + K5_XL;
    uint32_t* YH = sm5w + K5_YH;
    uint32_t* YL = sm5w + K5_YL;
    uint32_t* BH = sm5w + K5_B;
    uint32_t* BL = sm5w + K5_BL;

    const int tid = threadIdx.x, wid = tid >> 5, lane = tid & 31;
    const int g = lane >> 2, t = lane & 3;
    const int row0 = blockIdx.x * 64;
    const float tval = tptr[0];

    for (int i = tid; i < 64 * 64; i += 512) {
        int r = i >> 6, wi = i & 63;
        float x = 0.f, y = 0.f;
        if (row0 + r < N) {
            float2 v = ((const float2*)(h + (size_t)(row0 + r) * H))[wi];
            x = v.x; y = v.y;
        }
        uint32_t hh, ll; split2(x, y, hh, ll);
        XH[r * XS + wi] = hh; XL[r * XS + wi] = ll;
    }
    for (int i = tid; i < 64 * 16; i += 512) {
        int r = i >> 4, wi = i & 15;
        float x = __cosf(fmaf(tval, tfreq[wi * 2],     tphase[wi * 2]));
        float y = __cosf(fmaf(tval, tfreq[wi * 2 + 1], tphase[wi * 2 + 1]));
        uint32_t hh, ll; split2(x, y, hh, ll);
        XH[r * XS + 128 + wi] = hh; XL[r * XS + 128 + wi] = ll;
    }
    for (int i = tid; i < 64 * 64; i += 512) {
        int r = i >> 6, wi = i & 63;
        float x = 0.f, y = 0.f;
        if (row0 + r < N) {
            float2 v = ((const float2*)(g_agg + (size_t)(row0 + r) * H))[wi];
            x = v.x; y = v.y;
        }
        uint32_t hh, ll; split2(x, y, hh, ll);
        YH[r * YS + wi] = hh; YL[r * YS + wi] = ll;
    }

    // ======================= stage 0: agg @ wo ==============================
    {
        const int m0 = (wid & 3) * 16, n0 = (wid >> 2) * 32;
        float c[4][4];
        #pragma unroll
        for (int nt = 0; nt < 4; nt++)
            c[nt][0] = c[nt][1] = c[nt][2] = c[nt][3] = 0.f;
        for (int ks = 0; ks < 4; ks++) {
            __syncthreads();
            for (int i = tid; i < 16 * 128; i += 512) {
                int kp = i >> 7, n = i & 127;
                int k0 = ks * 32 + kp * 2;
                float x = wo[(size_t)k0 * H + n];
                float y = wo[(size_t)(k0 + 1) * H + n];
                uint32_t hh, ll; split2(x, y, hh, ll);
                BH[kp * 136 + n] = hh; BL[kp * 136 + n] = ll;
            }
            __syncthreads();
            #pragma unroll
            for (int kk = 0; kk < 2; kk++) {
                int aw = ks * 16 + kk * 8 + t;
                int ar0 = (m0 + g) * YS + aw, ar1 = (m0 + g + 8) * YS + aw;
                uint32_t ah[4] = { YH[ar0], YH[ar1], YH[ar0 + 4], YH[ar1 + 4] };
                uint32_t al[4] = { YL[ar0], YL[ar1], YL[ar0 + 4], YL[ar1 + 4] };
                int br0 = (kk * 8 + t) * 136, br1 = (kk * 8 + 4 + t) * 136;
                #pragma unroll
                for (int nt = 0; nt < 4; nt++) {
                    int nn = n0 + nt * 8 + g;
                    uint32_t bh0 = BH[br0 + nn], bh1 = BH[br1 + nn];
                    uint32_t bl0 = BL[br0 + nn], bl1 = BL[br1 + nn];
                    mma_bf16(c[nt], ah, bh0, bh1);
                    mma_bf16(c[nt], ah, bl0, bl1);
                    mma_bf16(c[nt], al, bh0, bh1);
                }
            }
        }
        #pragma unroll
        for (int nt = 0; nt < 4; nt++) {
            int wi = 64 + (n0 >> 1) + nt * 4 + t;
            uint32_t hh, ll;
            split2(c[nt][0], c[nt][1], hh, ll);
            XH[(m0 + g) * XS + wi] = hh; XL[(m0 + g) * XS + wi] = ll;
            split2(c[nt][2], c[nt][3], hh, ll);
            XH[(m0 + g + 8) * XS + wi] = hh; XL[(m0 + g + 8) * XS + wi] = ll;
        }
    }

    // ======================= stage 1: X @ w1 + b1, silu =====================
    {
        const int m0 = (wid & 3) * 16, n0 = (wid >> 2) * 64;
        float c[8][4];
        #pragma unroll
        for (int nt = 0; nt < 8; nt++)
            c[nt][0] = c[nt][1] = c[nt][2] = c[nt][3] = 0.f;
        for (int ks = 0; ks < 9; ks++) {
            __syncthreads();
            for (int i = tid; i < 16 * 256; i += 512) {
                int kp = i >> 8, n = i & 255;
                int k0 = ks * 32 + kp * 2;
                float x = w1[(size_t)k0 * MH + n];
                float y = w1[(size_t)(k0 + 1) * MH + n];
                uint32_t hh, ll; split2(x, y, hh, ll);
                BH[kp * 264 + n] = hh; BL[kp * 264 + n] = ll;
            }
            __syncthreads();
            #pragma unroll
            for (int kk = 0; kk < 2; kk++) {
                int aw = ks * 16 + kk * 8 + t;
                int ar0 = (m0 + g) * XS + aw, ar1 = (m0 + g + 8) * XS + aw;
                uint32_t ah[4] = { XH[ar0], XH[ar1], XH[ar0 + 4], XH[ar1 + 4] };
                uint32_t al[4] = { XL[ar0], XL[ar1], XL[ar0 + 4], XL[ar1 + 4] };
                int br0 = (kk * 8 + t) * 264, br1 = (kk * 8 + 4 + t) * 264;
                #pragma unroll
                for (int nt = 0; nt < 8; nt++) {
                    int nn = n0 + nt * 8 + g;
                    uint32_t bh0 = BH[br0 + nn], bh1 = BH[br1 + nn];
                    uint32_t bl0 = BL[br0 + nn], bl1 = BL[br1 + nn];
                    mma_bf16(c[nt], ah, bh0, bh1);
                    mma_bf16(c[nt], ah, bl0, bl1);
                    mma_bf16(c[nt], al, bh0, bh1);
                }
            }
        }
        #pragma unroll
        for (int nt = 0; nt < 8; nt++) {
            int col = n0 + nt * 8 + t * 2;
            float bx = b1[col], by = b1[col + 1];
            int wi = col >> 1;
            uint32_t hh, ll;
            split2(silu_f(c[nt][0] + bx), silu_f(c[nt][1] + by), hh, ll);
            YH[(m0 + g) * YS + wi] = hh; YL[(m0 + g) * YS + wi] = ll;
            split2(silu_f(c[nt][2] + bx), silu_f(c[nt][3] + by), hh, ll);
            YH[(m0 + g + 8) * YS + wi] = hh; YL[(m0 + g + 8) * YS + wi] = ll;
        }
    }

    // ======================= stage 2: Y @ w2 + b2, silu =====================
    {
        const int m0 = (wid & 3) * 16, n0 = (wid >> 2) * 64;
        float c[8][4];
        #pragma unroll
        for (int nt = 0; nt < 8; nt++)
            c[nt][0] = c[nt][1] = c[nt][2] = c[nt][3] = 0.f;
        for (int ks = 0; ks < 8; ks++) {
            __syncthreads();
            for (int i = tid; i < 16 * 256; i += 512) {
                int kp = i >> 8, n = i & 255;
                int k0 = ks * 32 + kp * 2;
                float x = w2[(size_t)k0 * MH + n];
                float y = w2[(size_t)(k0 + 1) * MH + n];
                uint32_t hh, ll; split2(x, y, hh, ll);
                BH[kp * 264 + n] = hh; BL[kp * 264 + n] = ll;
            }
            __syncthreads();
            #pragma unroll
            for (int kk = 0; kk < 2; kk++) {
                int aw = ks * 16 + kk * 8 + t;
                int ar0 = (m0 + g) * YS + aw, ar1 = (m0 + g + 8) * YS + aw;
                uint32_t ah[4] = { YH[ar0], YH[ar1], YH[ar0 + 4], YH[ar1 + 4] };
                uint32_t al[4] = { YL[ar0], YL[ar1], YL[ar0 + 4], YL[ar1 + 4] };
                int br0 = (kk * 8 + t) * 264, br1 = (kk * 8 + 4 + t) * 264;
                #pragma unroll
                for (int nt = 0; nt < 8; nt++) {
                    int nn = n0 + nt * 8 + g;
                    uint32_t bh0 = BH[br0 + nn], bh1 = BH[br1 + nn];
                    uint32_t bl0 = BL[br0 + nn], bl1 = BL[br1 + nn];
                    mma_bf16(c[nt], ah, bh0, bh1);
                    mma_bf16(c[nt], ah, bl0, bl1);
                    mma_bf16(c[nt], al, bh0, bh1);
                }
            }
        }
        #pragma unroll
        for (int nt = 0; nt < 8; nt++) {
            int col = n0 + nt * 8 + t * 2;
            float bx = b2[col], by = b2[col + 1];
            int wi = col >> 1;
            uint32_t hh, ll;
            split2(silu_f(c[nt][0] + bx), silu_f(c[nt][1] + by), hh, ll);
            XH[(m0 + g) * XS + wi] = hh; XL[(m0 + g) * XS + wi] = ll;
            split2(silu_f(c[nt][2] + bx), silu_f(c[nt][3] + by), hh, ll);
            XH[(m0 + g + 8) * XS + wi] = hh; XL[(m0 + g + 8) * XS + wi] = ll;
        }
    }

    // ======================= stage 3: X @ w3 + b3 -> out ====================
    {
        const int m0 = (wid & 3) * 16, n0 = (wid >> 2) * 32;
        float c[4][4];
        #pragma unroll
        for (int nt = 0; nt < 4; nt++)
            c[nt][0] = c[nt][1] = c[nt][2] = c[nt][3] = 0.f;
        for (int ks = 0; ks < 8; ks++) {
            __syncthreads();
            for (int i = tid; i < 16 * 128; i += 512) {
                int kp = i >> 7, n = i & 127;
                int k0 = ks * 32 + kp * 2;
                float x = w3[(size_t)k0 * H + n];
                float y = w3[(size_t)(k0 + 1) * H + n];
                uint32_t hh, ll; split2(x, y, hh, ll);
                BH[kp * 136 + n] = hh; BL[kp * 136 + n] = ll;
            }
            __syncthreads();
            #pragma unroll
            for (int kk = 0; kk < 2; kk++) {
                int aw = ks * 16 + kk * 8 + t;
                int ar0 = (m0 + g) * XS + aw, ar1 = (m0 + g + 8) * XS + aw;
                uint32_t ah[4] = { XH[ar0], XH[ar1], XH[ar0 + 4], XH[ar1 + 4] };
                uint32_t al[4] = { XL[ar0], XL[ar1], XL[ar0 + 4], XL[ar1 + 4] };
                int br0 = (kk * 8 + t) * 136, br1 = (kk * 8 + 4 + t) * 136;
                #pragma unroll
                for (int nt = 0; nt < 4; nt++) {
                    int nn = n0 + nt * 8 + g;
                    uint32_t bh0 = BH[br0 + nn], bh1 = BH[br1 + nn];
                    uint32_t bl0 = BL[br0 + nn], bl1 = BL[br1 + nn];
                    mma_bf16(c[nt], ah, bh0, bh1);
                    mma_bf16(c[nt], ah, bl0, bl1);
                    mma_bf16(c[nt], al, bh0, bh1);
                }
            }
        }
        int r1 = row0 + m0 + g, r2 = r1 + 8;
        #pragma unroll
        for (int nt = 0; nt < 4; nt++) {
            int col = n0 + nt * 8 + t * 2;
            float bx = b3[col], by = b3[col + 1];
            if (r1 < N) {
                out[(size_t)r1 * H + col]     = c[nt][0] + bx;
                out[(size_t)r1 * H + col + 1] = c[nt][1] + by;
            }
            if (r2 < N) {
                out[(size_t)r2 * H + col]     = c[nt][2] + bx;
                out[(size_t)r2 * H + col + 1] = c[nt][3] + by;
            }
        }
    }
}

// ============================================================================
extern "C" void kernel_launch(void* const* d_in, const int* in_sizes, int n_in,
                              void* d_out, int out_size)
{
    int wbase = (in_sizes[5] == (H + ED) * H) ? 5 : 6;

    const float* t_ptr  = (const float*)d_in[0];
    const float* h      = (const float*)d_in[1];
    const int*   eidx   = (const int*)  d_in[2];
    const float* ef     = (const float*)d_in[3];
    const float* dts    = (const float*)d_in[4];
    const float* msg_w1 = (const float*)d_in[wbase + 0];
    const float* msg_b1 = (const float*)d_in[wbase + 1];
    const float* msg_w2 = (const float*)d_in[wbase + 2];
    const float* msg_b2 = (const float*)d_in[wbase + 3];
    const float* wq     = (const float*)d_in[wbase + 4];
    const float* wk     = (const float*)d_in[wbase + 5];
    const float* wt     = (const float*)d_in[wbase + 6];
    const float* wo     = (const float*)d_in[wbase + 7];
    const float* tfreq  = (const float*)d_in[wbase + 8];
    const float* tphase = (const float*)d_in[wbase + 9];
    const float* nw1    = (const float*)d_in[wbase + 10];
    const float* nb1    = (const float*)d_in[wbase + 11];
    const float* nw2    = (const float*)d_in[wbase + 12];
    const float* nb2    = (const float*)d_in[wbase + 13];
    const float* nw3    = (const float*)d_in[wbase + 14];
    const float* nb3    = (const float*)d_in[wbase + 15];
    float* out = (float*)d_out;

    const int N = in_sizes[1] / H;
    const int E = in_sizes[4];

    void *p_smax, *p_den, *p_agg;
    cudaGetSymbolAddress(&p_smax, g_smax);
    cudaGetSymbolAddress(&p_den,  g_den);
    cudaGetSymbolAddress(&p_agg,  g_agg);
    cudaMemsetAsync(p_smax, 0, (size_t)N * NH * sizeof(unsigned), 0);
    cudaMemsetAsync(p_den,  0, (size_t)N * NH * sizeof(float), 0);
    cudaMemsetAsync(p_agg,  0, (size_t)N * H  * sizeof(float), 0);

    cudaFuncSetAttribute(k1_proj, cudaFuncAttributeMaxDynamicSharedMemorySize, SMEM1_BYTES);
    cudaFuncSetAttribute(k4_edge, cudaFuncAttributeMaxDynamicSharedMemorySize, SMEM4_BYTES);
    cudaFuncSetAttribute(k5_out,  cudaFuncAttributeMaxDynamicSharedMemorySize, SMEM5_BYTES);

    k1_proj<<<(N + 63) / 64, 256, SMEM1_BYTES>>>(h, wq, wk, msg_w1, msg_b1, N);
    k2_scores<<<1184, 256>>>(wt, tfreq, tphase, eidx, dts, E);
    k3_softmax<<<(E + 255) / 256, 256>>>(eidx, E);
    k4_edge<<<148, 512, SMEM4_BYTES>>>(ef, msg_w1 + H * H, msg_w2, msg_b2, eidx, E);
    k5_out<<<(N + 63) / 64, 512, SMEM5_BYTES>>>(h, wo, nw1, nb1, nw2, nb2,
                                                nw3, nb3, t_ptr, tfreq, tphase, out, N);
}